// round 7
// baseline (speedup 1.0000x reference)
#include <cuda_runtime.h>
#include <cstdint>
#include <math.h>

#define NTOK 4096
#define EDIM 1024
#define CDIM 1024
#define HDIM 4096
#define VDIM 32000
#define EPS_LN 1e-5f

// ---------------------------------------------------------------------------
// Static scratch
// ---------------------------------------------------------------------------
__device__ float g_x[NTOK * EDIM];
__device__ float g_ctx[NTOK * CDIM];
__device__ float g_dl[NTOK * CDIM];
__device__ float g_fg[NTOK * CDIM];
__device__ float g_ig[NTOK * CDIM];
__device__ float g_h[NTOK * HDIM];           // fp32 GEMM output scratch

// int8 activation limbs
__device__ int8_t g_c1[NTOK * 2048], g_c2[NTOK * 2048];     // cat
__device__ int8_t g_h1a[NTOK * HDIM], g_h1b[NTOK * HDIM];   // h1
__device__ int8_t g_h2a[NTOK * HDIM], g_h2b[NTOK * HDIM];   // h2
__device__ float g_sCat[NTOK], g_sH1[NTOK], g_sH2[NTOK];

// int8 weight limbs (transposed [N,K]) + per-output-column dequant scales
#define WT_TOTAL 193986560ULL
#define WSC_TOTAL 51456
__device__ int8_t g_w1[WT_TOTAL], g_w2[WT_TOTAL];
__device__ float g_wsc[WSC_TOTAL];

// ---------------------------------------------------------------------------
// helpers
// ---------------------------------------------------------------------------
__device__ __forceinline__ uint32_t smem_to_u32(const void* p) {
    uint32_t a;
    asm("{ .reg .u64 t; cvta.to.shared.u64 t, %1; cvt.u32.u64 %0, t; }"
        : "=r"(a) : "l"(p));
    return a;
}
__device__ __forceinline__ uint32_t swz(uint32_t o) { return o ^ ((o >> 3) & 0x70); }
__device__ __forceinline__ void cp_async16(uint32_t dst, const void* src) {
    asm volatile("cp.async.cg.shared.global [%0], [%1], 16;" :: "r"(dst), "l"(src));
}
template <int N>
__device__ __forceinline__ void cp_wait() {
    asm volatile("cp.async.wait_group %0;" :: "n"(N) : "memory");
}
__device__ __forceinline__ void cp_commit() {
    asm volatile("cp.async.commit_group;" ::: "memory");
}
__device__ __forceinline__ void ldsm_x4(uint32_t& a0, uint32_t& a1, uint32_t& a2,
                                        uint32_t& a3, uint32_t addr) {
    asm volatile("ldmatrix.sync.aligned.m8n8.x4.shared.b16 {%0,%1,%2,%3}, [%4];"
                 : "=r"(a0), "=r"(a1), "=r"(a2), "=r"(a3) : "r"(addr));
}
// int8 IMMA m16n8k32, s32 accumulate
__device__ __forceinline__ void mma_s8(int& d0, int& d1, int& d2, int& d3,
                                       uint32_t a0, uint32_t a1, uint32_t a2, uint32_t a3,
                                       uint32_t b0, uint32_t b1) {
    asm volatile(
        "mma.sync.aligned.m16n8k32.row.col.s32.s8.s8.s32 "
        "{%0,%1,%2,%3}, {%4,%5,%6,%7}, {%8,%9}, {%0,%1,%2,%3};"
        : "+r"(d0), "+r"(d1), "+r"(d2), "+r"(d3)
        : "r"(a0), "r"(a1), "r"(a2), "r"(a3), "r"(b0), "r"(b1));
}

// ---------------------------------------------------------------------------
// block reductions (256 threads)
// ---------------------------------------------------------------------------
__device__ __forceinline__ float block_sum256(float val) {
    __shared__ float sh[8];
    int lane = threadIdx.x & 31;
    #pragma unroll
    for (int o = 16; o > 0; o >>= 1) val += __shfl_xor_sync(0xffffffffu, val, o);
    if (lane == 0) sh[threadIdx.x >> 5] = val;
    __syncthreads();
    float t = (lane < 8) ? sh[lane] : 0.f;
    #pragma unroll
    for (int o = 4; o > 0; o >>= 1) t += __shfl_xor_sync(0xffffffffu, t, o);
    t = __shfl_sync(0xffffffffu, t, 0);
    __syncthreads();
    return t;
}
__device__ __forceinline__ float block_max256(float val) {
    __shared__ float sh[8];
    int lane = threadIdx.x & 31;
    #pragma unroll
    for (int o = 16; o > 0; o >>= 1)
        val = fmaxf(val, __shfl_xor_sync(0xffffffffu, val, o));
    if (lane == 0) sh[threadIdx.x >> 5] = val;
    __syncthreads();
    float t = (lane < 8) ? sh[lane] : 0.f;
    #pragma unroll
    for (int o = 4; o > 0; o >>= 1)
        t = fmaxf(t, __shfl_xor_sync(0xffffffffu, t, o));
    t = __shfl_sync(0xffffffffu, t, 0);
    __syncthreads();
    return t;
}

// ---------------------------------------------------------------------------
// small kernels
// ---------------------------------------------------------------------------
__global__ void embed_ln_kernel(const int* __restrict__ ids,
                                const float* __restrict__ tbl,
                                const float* __restrict__ gw,
                                const float* __restrict__ gb) {
    int row = blockIdx.x;
    size_t base = (size_t)ids[row] * EDIM;
    float v[4];
    float s = 0.f;
    #pragma unroll
    for (int i = 0; i < 4; i++) { v[i] = tbl[base + threadIdx.x + i * 256]; s += v[i]; }
    float mean = block_sum256(s) * (1.f / (float)EDIM);
    float s2 = 0.f;
    #pragma unroll
    for (int i = 0; i < 4; i++) { float d = v[i] - mean; s2 += d * d; }
    float rstd = rsqrtf(block_sum256(s2) * (1.f / (float)EDIM) + EPS_LN);
    #pragma unroll
    for (int i = 0; i < 4; i++) {
        int c = threadIdx.x + i * 256;
        g_x[(size_t)row * EDIM + c] = (v[i] - mean) * rstd * gw[c] + gb[c];
    }
}

__global__ void ctx_update_kernel(int first, const float* __restrict__ cg,
                                  const float* __restrict__ cb) {
    int row = blockIdx.x;
    size_t b = (size_t)row * CDIM;
    float v[4];
    float s = 0.f;
    #pragma unroll
    for (int i = 0; i < 4; i++) {
        int c = threadIdx.x + i * 256;
        float prev = first ? 0.f : g_fg[b + c] * g_ctx[b + c];
        v[i] = prev + g_ig[b + c] * g_dl[b + c];
        s += v[i];
    }
    float mean = block_sum256(s) * (1.f / (float)CDIM);
    float s2 = 0.f;
    #pragma unroll
    for (int i = 0; i < 4; i++) { float d = v[i] - mean; s2 += d * d; }
    float rstd = rsqrtf(block_sum256(s2) * (1.f / (float)CDIM) + EPS_LN);
    #pragma unroll
    for (int i = 0; i < 4; i++) {
        int c = threadIdx.x + i * 256;
        g_ctx[b + c] = (v[i] - mean) * rstd * cg[c] + cb[c];
    }
}

// quantize 2-limb int8: x = s*(q1 + q2/128), s = rowmax/127
__device__ __forceinline__ void quant2(float x, float inv, int& q1, int& q2) {
    float q = x * inv;
    float r1 = rintf(q);
    q1 = (int)r1;
    q2 = (int)rintf((q - r1) * 128.f);
}
__device__ __forceinline__ uint32_t pack4(int a, int b, int c, int d) {
    return (uint32_t)(a & 255) | ((uint32_t)(b & 255) << 8) |
           ((uint32_t)(c & 255) << 16) | ((uint32_t)(d & 255) << 24);
}

// cat = [x | ctx] -> int8 limbs + per-row scale. 1 block/row, 8 els/thread.
__global__ void catquant_kernel(int first, int8_t* __restrict__ q1,
                                int8_t* __restrict__ q2, float* __restrict__ sc) {
    int row = blockIdx.x, t = threadIdx.x;
    int c0 = t * 8;
    float v[8];
    if (c0 < 1024) {
        float4 u0 = *(const float4*)&g_x[(size_t)row * 1024 + c0];
        float4 u1 = *(const float4*)&g_x[(size_t)row * 1024 + c0 + 4];
        v[0]=u0.x; v[1]=u0.y; v[2]=u0.z; v[3]=u0.w;
        v[4]=u1.x; v[5]=u1.y; v[6]=u1.z; v[7]=u1.w;
    } else if (first) {
        #pragma unroll
        for (int i = 0; i < 8; i++) v[i] = 0.f;
    } else {
        float4 u0 = *(const float4*)&g_ctx[(size_t)row * 1024 + c0 - 1024];
        float4 u1 = *(const float4*)&g_ctx[(size_t)row * 1024 + c0 - 1020];
        v[0]=u0.x; v[1]=u0.y; v[2]=u0.z; v[3]=u0.w;
        v[4]=u1.x; v[5]=u1.y; v[6]=u1.z; v[7]=u1.w;
    }
    float m = 0.f;
    #pragma unroll
    for (int i = 0; i < 8; i++) m = fmaxf(m, fabsf(v[i]));
    m = fmaxf(block_max256(m), 1e-20f);
    if (t == 0) sc[row] = m * (1.f / 127.f);
    float inv = 127.f / m;
    int a[8], b[8];
    #pragma unroll
    for (int i = 0; i < 8; i++) quant2(v[i], inv, a[i], b[i]);
    *(uint2*)(q1 + (size_t)row * 2048 + c0) =
        make_uint2(pack4(a[0],a[1],a[2],a[3]), pack4(a[4],a[5],a[6],a[7]));
    *(uint2*)(q2 + (size_t)row * 2048 + c0) =
        make_uint2(pack4(b[0],b[1],b[2],b[3]), pack4(b[4],b[5],b[6],b[7]));
}

// g_h [NTOK, 4096] fp32 -> int8 limbs + per-row scale. 16 els/thread.
__global__ void hquant_kernel(int8_t* __restrict__ q1, int8_t* __restrict__ q2,
                              float* __restrict__ sc) {
    int row = blockIdx.x, t = threadIdx.x;
    int c0 = t * 16;
    float v[16];
    #pragma unroll
    for (int u = 0; u < 4; u++) {
        float4 w = *(const float4*)&g_h[(size_t)row * HDIM + c0 + u * 4];
        v[u*4+0]=w.x; v[u*4+1]=w.y; v[u*4+2]=w.z; v[u*4+3]=w.w;
    }
    float m = 0.f;
    #pragma unroll
    for (int i = 0; i < 16; i++) m = fmaxf(m, fabsf(v[i]));
    m = fmaxf(block_max256(m), 1e-20f);
    if (t == 0) sc[row] = m * (1.f / 127.f);
    float inv = 127.f / m;
    int a[16], b[16];
    #pragma unroll
    for (int i = 0; i < 16; i++) quant2(v[i], inv, a[i], b[i]);
    uint4 pa = make_uint4(pack4(a[0],a[1],a[2],a[3]),  pack4(a[4],a[5],a[6],a[7]),
                          pack4(a[8],a[9],a[10],a[11]), pack4(a[12],a[13],a[14],a[15]));
    uint4 pb = make_uint4(pack4(b[0],b[1],b[2],b[3]),  pack4(b[4],b[5],b[6],b[7]),
                          pack4(b[8],b[9],b[10],b[11]), pack4(b[12],b[13],b[14],b[15]));
    *(uint4*)(q1 + (size_t)row * HDIM + c0) = pa;
    *(uint4*)(q2 + (size_t)row * HDIM + c0) = pb;
}

// ---------------------------------------------------------------------------
// Weight conversion: 8 jobs (block-1 gate weights are dead code -> skipped)
// ---------------------------------------------------------------------------
#define NJOB 8
struct WJobs {
    const float* W[NJOB];
    long long eoff[NJOB];   // element offset in weight arena
    int roff[NJOB];         // row offset in g_wsc
    int K[NJOB];
    int N[NJOB];
    int startS[NJOB + 1];   // colmax strips (N/32 each)
    int startT[NJOB + 1];   // transpose tiles (N/32 * K/32 each)
};

__global__ void zero_wsc_kernel() {
    int i = blockIdx.x * blockDim.x + threadIdx.x;
    if (i < WSC_TOTAL) g_wsc[i] = 1e-20f;
}

// per-output-column DEQUANT SCALE = colmax/127 (FIX: was raw colmax)
__global__ void colmax_kernel(WJobs jobs) {
    int b = blockIdx.x;
    int ji = 0;
    #pragma unroll
    for (int j = 0; j < NJOB; j++) if (b >= jobs.startS[j + 1]) ji = j + 1;
    const float* W = jobs.W[ji];
    const int K = jobs.K[ji], N = jobs.N[ji];
    int n0 = (b - jobs.startS[ji]) * 32;
    int tx = threadIdx.x & 31, ty = threadIdx.x >> 5;
    float m = 0.f;
    for (int k = ty; k < K; k += 8)
        m = fmaxf(m, fabsf(W[(size_t)k * N + n0 + tx]));
    __shared__ float sh[8][32];
    sh[ty][tx] = m;
    __syncthreads();
    if (ty == 0) {
        #pragma unroll
        for (int i = 1; i < 8; i++) m = fmaxf(m, sh[i][tx]);
        g_wsc[jobs.roff[ji] + n0 + tx] = fmaxf(m, 1e-20f) * (1.f / 127.f);
    }
}

// transpose + quantize: W[K,N] fp32 -> limbs [N,K] int8
__global__ void wquant_kernel(WJobs jobs) {
    __shared__ float t[32][33];
    int b = blockIdx.x;
    int ji = 0;
    #pragma unroll
    for (int j = 0; j < NJOB; j++) if (b >= jobs.startT[j + 1]) ji = j + 1;
    const float* W = jobs.W[ji];
    const int K = jobs.K[ji], N = jobs.N[ji];
    const long long eoff = jobs.eoff[ji];
    int tno = b - jobs.startT[ji];
    int ntiles = N >> 5;
    int n0 = (tno % ntiles) << 5, k0 = (tno / ntiles) << 5;
    int tx = threadIdx.x & 31, ty = threadIdx.x >> 5;
    #pragma unroll
    for (int i = 0; i < 4; i++) {
        int kk = ty + i * 8;
        t[kk][tx] = W[(size_t)(k0 + kk) * N + n0 + tx];
    }
    __syncthreads();
    #pragma unroll
    for (int i = 0; i < 4; i++) {
        int nn = ty + i * 8;
        // g_wsc holds dequant scale (= colmax/127); quantization inv = 1/scale
        float inv = 1.f / g_wsc[jobs.roff[ji] + n0 + nn];
        int q1, q2;
        quant2(t[tx][nn], inv, q1, q2);
        size_t o = (size_t)eoff + (size_t)(n0 + nn) * K + k0 + tx;
        g_w1[o] = (int8_t)q1;
        g_w2[o] = (int8_t)q2;
    }
}

// ---------------------------------------------------------------------------
// int8 3-product GEMM: C[M,N] = act(sA*sW*(hi + mid/128) + bias)
// Block 128x128, BK=128 int8, 8 warps (2x4), warp tile 64x32.
// Stage: A1|A2|B1|B2 each 128x128B = 64KB; 3-stage cp.async pipeline.
// ---------------------------------------------------------------------------
#define STAGE_BYTES 65536
#define OFF_A2 16384
#define OFF_B1 32768
#define OFF_B2 49152
#define GEMM_SMEM (3 * STAGE_BYTES)

template <int EPI>
__device__ __forceinline__ float epi_act(float x) {
    if (EPI == 1) return fmaxf(x, 0.f);
    if (EPI == 2) return tanhf(x);
    if (EPI == 3) return 1.f / (1.f + expf(-x));
    return x;
}

template <int EPI>
__global__ void __launch_bounds__(256, 1)
gemm_s8x3(const int8_t* __restrict__ a1, const int8_t* __restrict__ a2,
          const int8_t* __restrict__ w1, const int8_t* __restrict__ w2,
          const float* __restrict__ sA, const float* __restrict__ sW,
          const float* __restrict__ bias, float* __restrict__ outF,
          int N, int K) {
    extern __shared__ char smem[];
    const uint32_t sbase = smem_to_u32(smem);
    const int tid = threadIdx.x, wid = tid >> 5, lane = tid & 31;
    const int warp_m = wid & 1, warp_n = wid >> 1;
    const int rowBase = blockIdx.x * 128;
    const int colBase = blockIdx.y * 128;

    int hi[4][4][4], mi[4][4][4];
    #pragma unroll
    for (int i = 0; i < 4; i++)
        #pragma unroll
        for (int j = 0; j < 4; j++)
            #pragma unroll
            for (int u = 0; u < 4; u++) { hi[i][j][u] = 0; mi[i][j][u] = 0; }

    const int nk = K >> 7;

    const int aRow = warp_m * 64 + (lane & 15);
    const int aByte = (lane >> 4) << 4;
    const int bRow = warp_n * 32 + ((lane >> 4) << 3) + (lane & 7);
    const int bByte = ((lane >> 3) & 1) << 4;

    auto fill = [&](int kt) {
        const uint32_t st = sbase + (kt % 3) * STAGE_BYTES;
        const int k0 = kt << 7;
        #pragma unroll
        for (int i = 0; i < 16; i++) {
            int o = tid + (i << 8);
            int q = o & 1023, r = q >> 3, c = q & 7;
            const int8_t* src;
            uint32_t dst;
            if (o < 1024) {
                src = a1 + (size_t)(rowBase + r) * K + k0 + c * 16;
                dst = st + swz(r * 128 + c * 16);
            } else if (o < 2048) {
                src = a2 + (size_t)(rowBase + r) * K + k0 + c * 16;
                dst = st + OFF_A2 + swz(r * 128 + c * 16);
            } else if (o < 3072) {
                src = w1 + (size_t)(colBase + r) * K + k0 + c * 16;
                dst = st + OFF_B1 + swz(r * 128 + c * 16);
            } else {
                src = w2 + (size_t)(colBase + r) * K + k0 + c * 16;
                dst = st + OFF_B2 + swz(r * 128 + c * 16);
            }
            cp_async16(dst, src);
        }
        cp_commit();
    };

    fill(0);
    fill(1);
    for (int kt = 0; kt < nk; kt++) {
        if (kt + 1 < nk) cp_wait<1>();
        else             cp_wait<0>();
        __syncthreads();
        if (kt + 2 < nk) fill(kt + 2);

        const uint32_t st = sbase + (kt % 3) * STAGE_BYTES;
        #pragma unroll
        for (int ks = 0; ks < 4; ks++) {
            uint32_t af[4][4], bf[4][2];
            #pragma unroll
            for (int i = 0; i < 4; i++)
                ldsm_x4(af[i][0], af[i][1], af[i][2], af[i][3],
                        st + swz((aRow + i * 16) * 128 + ks * 32 + aByte));
            #pragma unroll
            for (int jj = 0; jj < 2; jj++)
                ldsm_x4(bf[2*jj][0], bf[2*jj][1], bf[2*jj+1][0], bf[2*jj+1][1],
                        st + OFF_B1 + swz((bRow + jj * 16) * 128 + ks * 32 + bByte));
            // hi += a1 * w1
            #pragma unroll
            for (int i = 0; i < 4; i++)
                #pragma unroll
                for (int j = 0; j < 4; j++)
                    mma_s8(hi[i][j][0], hi[i][j][1], hi[i][j][2], hi[i][j][3],
                           af[i][0], af[i][1], af[i][2], af[i][3], bf[j][0], bf[j][1]);
            // mid += a1 * w2
            {
                uint32_t b2f[4][2];
                #pragma unroll
                for (int jj = 0; jj < 2; jj++)
                    ldsm_x4(b2f[2*jj][0], b2f[2*jj][1], b2f[2*jj+1][0], b2f[2*jj+1][1],
                            st + OFF_B2 + swz((bRow + jj * 16) * 128 + ks * 32 + bByte));
                #pragma unroll
                for (int i = 0; i < 4; i++)
                    #pragma unroll
                    for (int j = 0; j < 4; j++)
                        mma_s8(mi[i][j][0], mi[i][j][1], mi[i][j][2], mi[i][j][3],
                               af[i][0], af[i][1], af[i][2], af[i][3], b2f[j][0], b2f[j][1]);
            }
            // mid += a2 * w1
            {
                uint32_t a2f[4][4];
                #pragma unroll
                for (int i = 0; i < 4; i++)
                    ldsm_x4(a2f[i][0], a2f[i][1], a2f[i][2], a2f[i][3],
                            st + OFF_A2 + swz((aRow + i * 16) * 128 + ks * 32 + aByte));
                #pragma unroll
                for (int i = 0; i < 4; i++)
                    #pragma unroll
                    for (int j = 0; j < 4; j++)
                        mma_s8(mi[i][j][0], mi[i][j][1], mi[i][j][2], mi[i][j][3],
                               a2f[i][0], a2f[i][1], a2f[i][2], a2f[i][3], bf[j][0], bf[j][1]);
            }
        }
        __syncthreads();
    }

    // epilogue: dequant + bias + activation
    const int erow = rowBase + warp_m * 64 + (lane >> 2);
    const int ecol = colBase + warp_n * 32 + (lane & 3) * 2;
    #pragma unroll
    for (int i = 0; i < 4; i++) {
        #pragma unroll
        for (int j = 0; j < 4; j++) {
            int col = ecol + j * 8;
            float sw0 = sW[col], sw1 = sW[col + 1];
            float b0 = bias[col], b1 = bias[col + 1];
            #pragma unroll
            for (int h = 0; h < 2; h++) {
                int r = erow + i * 16 + h * 8;
                float sa = sA[r];
                float v0 = epi_act<EPI>(
                    sa * sw0 * ((float)hi[i][j][2*h+0] + (float)mi[i][j][2*h+0] * 0.0078125f) + b0);
                float v1 = epi_act<EPI>(
                    sa * sw1 * ((float)hi[i][j][2*h+1] + (float)mi[i][j][2*h+1] * 0.0078125f) + b1);
                *(float2*)(outF + (size_t)r * N + col) = make_float2(v0, v1);
            }
        }
    }
}

// ---------------------------------------------------------------------------
// Launch
// ---------------------------------------------------------------------------
extern "C" void kernel_launch(void* const* d_in, const int* in_sizes, int n_in,
                              void* d_out, int out_size) {
    (void)in_sizes; (void)n_in; (void)out_size;

    const int*   ids  = (const int*)d_in[0];
    const float* tbl  = (const float*)d_in[1];
    const float* en_g = (const float*)d_in[2];
    const float* en_b = (const float*)d_in[3];
    const float* wA[2] = {(const float*)d_in[4],  (const float*)d_in[8]};
    const float* bA[2] = {(const float*)d_in[5],  (const float*)d_in[9]};
    const float* wB[2] = {(const float*)d_in[6],  (const float*)d_in[10]};
    const float* bB[2] = {(const float*)d_in[7],  (const float*)d_in[11]};
    const float* dw0 = (const float*)d_in[12];
    const float* db0 = (const float*)d_in[13];
    const float* fw0 = (const float*)d_in[14];
    const float* fb0 = (const float*)d_in[15];
    const float* iw0 = (const float*)d_in[16];
    const float* ib0 = (const float*)d_in[17];
    const float* cg0 = (const float*)d_in[18];
    const float* cb0 = (const float*)d_in[19];
    const float* ow = (const float*)d_in[28];
    const float* ob = (const float*)d_in[29];
    float* out = (float*)d_out;

    float *pdl, *pfg, *pig, *ph, *psCat, *psH1, *psH2, *pwsc;
    int8_t *pc1, *pc2, *ph1a, *ph1b, *ph2a, *ph2b, *pw1, *pw2;
    cudaGetSymbolAddress((void**)&pdl,  g_dl);
    cudaGetSymbolAddress((void**)&pfg,  g_fg);
    cudaGetSymbolAddress((void**)&pig,  g_ig);
    cudaGetSymbolAddress((void**)&ph,   g_h);
    cudaGetSymbolAddress((void**)&pc1,  g_c1);
    cudaGetSymbolAddress((void**)&pc2,  g_c2);
    cudaGetSymbolAddress((void**)&ph1a, g_h1a);
    cudaGetSymbolAddress((void**)&ph1b, g_h1b);
    cudaGetSymbolAddress((void**)&ph2a, g_h2a);
    cudaGetSymbolAddress((void**)&ph2b, g_h2b);
    cudaGetSymbolAddress((void**)&psCat, g_sCat);
    cudaGetSymbolAddress((void**)&psH1, g_sH1);
    cudaGetSymbolAddress((void**)&psH2, g_sH2);
    cudaGetSymbolAddress((void**)&pwsc, g_wsc);
    cudaGetSymbolAddress((void**)&pw1,  g_w1);
    cudaGetSymbolAddress((void**)&pw2,  g_w2);

    cudaFuncSetAttribute(gemm_s8x3<0>, cudaFuncAttributeMaxDynamicSharedMemorySize, GEMM_SMEM);
    cudaFuncSetAttribute(gemm_s8x3<1>, cudaFuncAttributeMaxDynamicSharedMemorySize, GEMM_SMEM);
    cudaFuncSetAttribute(gemm_s8x3<2>, cudaFuncAttributeMaxDynamicSharedMemorySize, GEMM_SMEM);
    cudaFuncSetAttribute(gemm_s8x3<3>, cudaFuncAttributeMaxDynamicSharedMemorySize, GEMM_SMEM);

    // jobs: wA0, wB0, dw0, fw0, iw0, wA1, wB1, ow  (block-1 gates are dead code)
    WJobs jobs;
    {
        const float* ws[NJOB] = {wA[0], wB[0], dw0, fw0, iw0, wA[1], wB[1], ow};
        const long long eo[NJOB] = {0, 8388608, 25165824, 29360128, 33554432,
                                    37748736, 46137344, 62914560};
        const int ro[NJOB] = {0, 4096, 8192, 9216, 10240, 11264, 15360, 19456};
        const int Ks[NJOB] = {2048, 4096, 4096, 4096, 4096, 2048, 4096, 4096};
        const int Ns[NJOB] = {4096, 4096, 1024, 1024, 1024, 4096, 4096, 32000};
        int cs = 0, ct = 0;
        for (int j = 0; j < NJOB; j++) {
            jobs.W[j] = ws[j]; jobs.eoff[j] = eo[j]; jobs.roff[j] = ro[j];
            jobs.K[j] = Ks[j]; jobs.N[j] = Ns[j];
            jobs.startS[j] = cs; jobs.startT[j] = ct;
            cs += Ns[j] >> 5;
            ct += (Ns[j] >> 5) * (Ks[j] >> 5);
        }
        jobs.startS[NJOB] = cs; jobs.startT[NJOB] = ct;

        zero_wsc_kernel<<<(WSC_TOTAL + 255) / 256, 256>>>();
        colmax_kernel<<<cs, 256>>>(jobs);
        wquant_kernel<<<ct, 256>>>(jobs);
    }

    const long long EO_WA[2] = {0, 37748736};
    const long long EO_WB[2] = {8388608, 46137344};
    const long long EO_DW = 25165824, EO_FW = 29360128, EO_IW = 33554432;
    const long long EO_OW = 62914560;
    const int RO_WA[2] = {0, 11264};
    const int RO_WB[2] = {4096, 15360};
    const int RO_DW = 8192, RO_FW = 9216, RO_IW = 10240, RO_OW = 19456;

    embed_ln_kernel<<<NTOK, 256>>>(ids, tbl, en_g, en_b);

    for (int blk = 0; blk < 2; blk++) {
        catquant_kernel<<<NTOK, 256>>>(blk == 0 ? 1 : 0, pc1, pc2, psCat);
        // h1 = relu(cat @ wA + bA)
        gemm_s8x3<1><<<dim3(NTOK / 128, HDIM / 128), 256, GEMM_SMEM>>>(
            pc1, pc2, pw1 + EO_WA[blk], pw2 + EO_WA[blk], psCat, pwsc + RO_WA[blk],
            bA[blk], ph, HDIM, EDIM + CDIM);
        hquant_kernel<<<NTOK, 256>>>(ph1a, ph1b, psH1);
        // h2 = relu(h1 @ wB + bB)
        gemm_s8x3<1><<<dim3(NTOK / 128, HDIM / 128), 256, GEMM_SMEM>>>(
            ph1a, ph1b, pw1 + EO_WB[blk], pw2 + EO_WB[blk], psH1, pwsc + RO_WB[blk],
            bB[blk], ph, HDIM, HDIM);
        hquant_kernel<<<NTOK, 256>>>(ph2a, ph2b, psH2);
        if (blk == 0) {
            // gates (only block 0's ctx is ever consumed)
            gemm_s8x3<2><<<dim3(NTOK / 128, CDIM / 128), 256, GEMM_SMEM>>>(
                ph2a, ph2b, pw1 + EO_DW, pw2 + EO_DW, psH2, pwsc + RO_DW,
                db0, pdl, CDIM, HDIM);
            gemm_s8x3<3><<<dim3(NTOK / 128, CDIM / 128), 256, GEMM_SMEM>>>(
                ph2a, ph2b, pw1 + EO_FW, pw2 + EO_FW, psH2, pwsc + RO_FW,
                fb0, pfg, CDIM, HDIM);
            gemm_s8x3<3><<<dim3(NTOK / 128, CDIM / 128), 256, GEMM_SMEM>>>(
                ph2a, ph2b, pw1 + EO_IW, pw2 + EO_IW, psH2, pwsc + RO_IW,
                ib0, pig, CDIM, HDIM);
            ctx_update_kernel<<<NTOK, 256>>>(1, cg0, cb0);
        }
    }

    // logits = h2(block 1) @ ow + ob
    gemm_s8x3<0><<<dim3(NTOK / 128, VDIM / 128), 256, GEMM_SMEM>>>(
        ph2a, ph2b, pw1 + EO_OW, pw2 + EO_OW, psH2, pwsc + RO_OW,
        ob, out, VDIM, HDIM);
}

// round 8
// speedup vs baseline: 4.3784x; 4.3784x over previous
#include <cuda_runtime.h>
#include <cuda_fp16.h>
#include <cstdint>
#include <math.h>

#define NTOK 4096
#define EDIM 1024
#define CDIM 1024
#define HDIM 4096
#define VDIM 32000
#define EPS_LN 1e-5f

// ---------------------------------------------------------------------------
// Static scratch
// ---------------------------------------------------------------------------
__device__ float g_x[NTOK * EDIM];
__device__ float g_ctx[NTOK * CDIM];
__device__ float g_dl[NTOK * CDIM];
__device__ float g_fg[NTOK * CDIM];
__device__ float g_ig[NTOK * CDIM];

// activation ping-pong buffers, split hi/lo fp16
__device__ __half g_act_hi0[NTOK * HDIM];
__device__ __half g_act_lo0[NTOK * HDIM];
__device__ __half g_act_hi1[NTOK * HDIM];
__device__ __half g_act_lo1[NTOK * HDIM];

// transposed weights [N,K], single fp16 limb (8 live jobs; block-1 gates dead)
#define WT_TOTAL 193986560ULL
__device__ __half g_wt[WT_TOTAL];

// ---------------------------------------------------------------------------
// helpers
// ---------------------------------------------------------------------------
__device__ __forceinline__ uint32_t smem_to_u32(const void* p) {
    uint32_t a;
    asm("{ .reg .u64 t; cvta.to.shared.u64 t, %1; cvt.u32.u64 %0, t; }"
        : "=r"(a) : "l"(p));
    return a;
}
__device__ __forceinline__ uint32_t swz(uint32_t o) { return o ^ ((o >> 3) & 0x70); }
__device__ __forceinline__ void cp_async16(uint32_t dst, const void* src) {
    asm volatile("cp.async.cg.shared.global [%0], [%1], 16;" :: "r"(dst), "l"(src));
}
template <int N>
__device__ __forceinline__ void cp_wait() {
    asm volatile("cp.async.wait_group %0;" :: "n"(N) : "memory");
}
__device__ __forceinline__ void cp_commit() {
    asm volatile("cp.async.commit_group;" ::: "memory");
}
__device__ __forceinline__ void ldsm_x4(uint32_t& a0, uint32_t& a1, uint32_t& a2,
                                        uint32_t& a3, uint32_t addr) {
    asm volatile("ldmatrix.sync.aligned.m8n8.x4.shared.b16 {%0,%1,%2,%3}, [%4];"
                 : "=r"(a0), "=r"(a1), "=r"(a2), "=r"(a3) : "r"(addr));
}
// fp16 MMA, fp32 accumulators
__device__ __forceinline__ void mma_f16(float& d0, float& d1, float& d2, float& d3,
                                        uint32_t a0, uint32_t a1, uint32_t a2, uint32_t a3,
                                        uint32_t b0, uint32_t b1) {
    asm volatile(
        "mma.sync.aligned.m16n8k16.row.col.f32.f16.f16.f32 "
        "{%0,%1,%2,%3}, {%4,%5,%6,%7}, {%8,%9}, {%0,%1,%2,%3};"
        : "+f"(d0), "+f"(d1), "+f"(d2), "+f"(d3)
        : "r"(a0), "r"(a1), "r"(a2), "r"(a3), "r"(b0), "r"(b1));
}
// fp16 MMA, fp16 accumulators (lo-limb pass; term is ~2^-11 of result)
__device__ __forceinline__ void mma_f16acc(uint32_t& c0, uint32_t& c1,
                                           uint32_t a0, uint32_t a1, uint32_t a2, uint32_t a3,
                                           uint32_t b0, uint32_t b1) {
    asm volatile(
        "mma.sync.aligned.m16n8k16.row.col.f16.f16.f16.f16 "
        "{%0,%1}, {%2,%3,%4,%5}, {%6,%7}, {%0,%1};"
        : "+r"(c0), "+r"(c1)
        : "r"(a0), "r"(a1), "r"(a2), "r"(a3), "r"(b0), "r"(b1));
}

// ---------------------------------------------------------------------------
// block reductions
// ---------------------------------------------------------------------------
__device__ __forceinline__ float block_sum256(float val) {
    __shared__ float sh[8];
    int lane = threadIdx.x & 31;
    #pragma unroll
    for (int o = 16; o > 0; o >>= 1) val += __shfl_xor_sync(0xffffffffu, val, o);
    if (lane == 0) sh[threadIdx.x >> 5] = val;
    __syncthreads();
    float t = (lane < 8) ? sh[lane] : 0.f;
    #pragma unroll
    for (int o = 4; o > 0; o >>= 1) t += __shfl_xor_sync(0xffffffffu, t, o);
    t = __shfl_sync(0xffffffffu, t, 0);
    __syncthreads();
    return t;
}

// ---------------------------------------------------------------------------
// small kernels
// ---------------------------------------------------------------------------
__global__ void embed_ln_kernel(const int* __restrict__ ids,
                                const float* __restrict__ tbl,
                                const float* __restrict__ gw,
                                const float* __restrict__ gb) {
    int row = blockIdx.x;
    size_t base = (size_t)ids[row] * EDIM;
    float v[4];
    float s = 0.f;
    #pragma unroll
    for (int i = 0; i < 4; i++) { v[i] = tbl[base + threadIdx.x + i * 256]; s += v[i]; }
    float mean = block_sum256(s) * (1.f / (float)EDIM);
    float s2 = 0.f;
    #pragma unroll
    for (int i = 0; i < 4; i++) { float d = v[i] - mean; s2 += d * d; }
    float rstd = rsqrtf(block_sum256(s2) * (1.f / (float)EDIM) + EPS_LN);
    #pragma unroll
    for (int i = 0; i < 4; i++) {
        int c = threadIdx.x + i * 256;
        g_x[(size_t)row * EDIM + c] = (v[i] - mean) * rstd * gw[c] + gb[c];
    }
}

// ctx = LN(i*delta) for block 0 (ctx starts at zero)
__global__ void ctx_update_kernel(const float* __restrict__ cg,
                                  const float* __restrict__ cb) {
    int row = blockIdx.x;
    size_t b = (size_t)row * CDIM;
    float v[4];
    float s = 0.f;
    #pragma unroll
    for (int i = 0; i < 4; i++) {
        int c = threadIdx.x + i * 256;
        v[i] = g_ig[b + c] * g_dl[b + c];
        s += v[i];
    }
    float mean = block_sum256(s) * (1.f / (float)CDIM);
    float s2 = 0.f;
    #pragma unroll
    for (int i = 0; i < 4; i++) { float d = v[i] - mean; s2 += d * d; }
    float rstd = rsqrtf(block_sum256(s2) * (1.f / (float)CDIM) + EPS_LN);
    #pragma unroll
    for (int i = 0; i < 4; i++) {
        int c = threadIdx.x + i * 256;
        g_ctx[b + c] = (v[i] - mean) * rstd * cg[c] + cb[c];
    }
}

__device__ __forceinline__ void split2h(float x0, float x1, uint32_t& hp, uint32_t& lp) {
    __half h0 = __float2half(x0), h1 = __float2half(x1);
    __half l0 = __float2half(x0 - __half2float(h0));
    __half l1 = __float2half(x1 - __half2float(h1));
    __half2 hh; hh.x = h0; hh.y = h1;
    __half2 ll; ll.x = l0; ll.y = l1;
    hp = *(uint32_t*)&hh; lp = *(uint32_t*)&ll;
}

// cat = [x | (first ? 0 : ctx)] -> hi/lo fp16, row stride 2048
__global__ void cat_split_kernel(int first, __half* __restrict__ hi,
                                 __half* __restrict__ lo) {
    int idx = blockIdx.x * blockDim.x + threadIdx.x;
    int row = idx >> 9, c4 = idx & 511;
    float4 v;
    if (c4 < 256)      v = ((const float4*)g_x)[row * 256 + c4];
    else if (first)    v = make_float4(0.f, 0.f, 0.f, 0.f);
    else               v = ((const float4*)g_ctx)[row * 256 + (c4 - 256)];
    uint32_t hp0, lp0, hp1, lp1;
    split2h(v.x, v.y, hp0, lp0);
    split2h(v.z, v.w, hp1, lp1);
    *(uint2*)(hi + (size_t)row * 2048 + c4 * 4) = make_uint2(hp0, hp1);
    *(uint2*)(lo + (size_t)row * 2048 + c4 * 4) = make_uint2(lp0, lp1);
}

// ---------------------------------------------------------------------------
// Fused weight conversion: 8 live jobs, W[K,N] fp32 -> Wt[N,K] fp16
// ---------------------------------------------------------------------------
#define NJOB 8
struct WJobs {
    const float* W[NJOB];
    long long off[NJOB];
    int K[NJOB];
    int N[NJOB];
    int start[NJOB + 1];
};

__global__ void wsplit_all_kernel(WJobs jobs, __half* __restrict__ T) {
    __shared__ float t[32][33];
    int b = blockIdx.x;
    int ji = 0;
    #pragma unroll
    for (int j = 0; j < NJOB; j++) if (b >= jobs.start[j + 1]) ji = j + 1;
    const float* W = jobs.W[ji];
    const int K = jobs.K[ji], N = jobs.N[ji];
    const long long off = jobs.off[ji];
    int tno = b - jobs.start[ji];
    int ntiles = N >> 5;
    int n0 = (tno % ntiles) << 5, k0 = (tno / ntiles) << 5;
    int tx = threadIdx.x & 31, ty = threadIdx.x >> 5;
    #pragma unroll
    for (int i = 0; i < 4; i++) {
        int kk = ty + i * 8;
        t[kk][tx] = W[(size_t)(k0 + kk) * N + n0 + tx];
    }
    __syncthreads();
    #pragma unroll
    for (int i = 0; i < 4; i++) {
        int nn = ty + i * 8;
        T[(size_t)off + (size_t)(n0 + nn) * K + k0 + tx] = __float2half(t[tx][nn]);
    }
}

// ---------------------------------------------------------------------------
// fp16 GEMM: C[M,N] = act(A @ W^T + bias)
// A split hi/lo fp16 [M,K]; W single fp16 limb [N,K].
// Block 128x128, BK=64, 8 warps (2x4), warp tile 64x32.
// NPASS=2: hi pass (f32 acc) + lo pass (f16 acc). NPASS=1: hi only.
// Stage: Ahi|Alo|B each 16KB = 48KB; 3-stage cp.async pipeline.
// ---------------------------------------------------------------------------
#define STAGE_BYTES 49152
#define OFF_ALO 16384
#define OFF_B 32768
#define GEMM_SMEM (3 * STAGE_BYTES)

template <int EPI>
__device__ __forceinline__ float epi_act(float x) {
    if (EPI == 1) return fmaxf(x, 0.f);
    if (EPI == 2) return tanhf(x);
    if (EPI == 3) return 1.f / (1.f + expf(-x));
    return x;
}

template <int EPI, int SPLIT, int NPASS>
__global__ void __launch_bounds__(256, 1)
gemm_f16(const __half* __restrict__ aHi, const __half* __restrict__ aLo,
         const __half* __restrict__ bW,
         const float* __restrict__ bias,
         float* __restrict__ outF,
         __half* __restrict__ oHi, __half* __restrict__ oLo,
         int N, int K) {
    extern __shared__ char smem[];
    const uint32_t sbase = smem_to_u32(smem);
    const int tid = threadIdx.x, wid = tid >> 5, lane = tid & 31;
    const int warp_m = wid & 1, warp_n = wid >> 1;
    const int rowBase = blockIdx.x * 128;
    const int colBase = blockIdx.y * 128;

    float acc[4][4][4];
    uint32_t accl[4][4][2];
    #pragma unroll
    for (int i = 0; i < 4; i++)
        #pragma unroll
        for (int j = 0; j < 4; j++) {
            #pragma unroll
            for (int u = 0; u < 4; u++) acc[i][j][u] = 0.f;
            accl[i][j][0] = 0u; accl[i][j][1] = 0u;
        }

    const int nk = K >> 6;

    const int aRow = warp_m * 64 + (lane & 15);
    const int aByte = (lane >> 4) << 4;
    const int bRow = warp_n * 32 + ((lane >> 4) << 3) + (lane & 7);
    const int bByte = ((lane >> 3) & 1) << 4;

    auto fill = [&](int kt) {
        const uint32_t st = sbase + (kt % 3) * STAGE_BYTES;
        const int k0 = kt << 6;
        const int chunks = (NPASS == 2) ? 12 : 8;
        #pragma unroll
        for (int i = 0; i < chunks; i++) {
            int o = tid + (i << 8);
            int q = o & 1023, r = q >> 3, c = q & 7;
            const __half* src;
            uint32_t dst;
            if (NPASS == 2) {
                if (o < 1024) {
                    src = aHi + (size_t)(rowBase + r) * K + k0 + c * 8;
                    dst = st + swz(r * 128 + c * 16);
                } else if (o < 2048) {
                    src = aLo + (size_t)(rowBase + r) * K + k0 + c * 8;
                    dst = st + OFF_ALO + swz(r * 128 + c * 16);
                } else {
                    src = bW + (size_t)(colBase + r) * K + k0 + c * 8;
                    dst = st + OFF_B + swz(r * 128 + c * 16);
                }
            } else {
                if (o < 1024) {
                    src = aHi + (size_t)(rowBase + r) * K + k0 + c * 8;
                    dst = st + swz(r * 128 + c * 16);
                } else {
                    src = bW + (size_t)(colBase + r) * K + k0 + c * 8;
                    dst = st + OFF_B + swz(r * 128 + c * 16);
                }
            }
            cp_async16(dst, src);
        }
        cp_commit();
    };

    fill(0);
    fill(1);
    for (int kt = 0; kt < nk; kt++) {
        if (kt + 1 < nk) cp_wait<1>();
        else             cp_wait<0>();
        __syncthreads();
        if (kt + 2 < nk) fill(kt + 2);

        const uint32_t st = sbase + (kt % 3) * STAGE_BYTES;
        #pragma unroll
        for (int ks = 0; ks < 4; ks++) {
            uint32_t af[4][4], bf[4][2];
            #pragma unroll
            for (int i = 0; i < 4; i++)
                ldsm_x4(af[i][0], af[i][1], af[i][2], af[i][3],
                        st + swz((aRow + i * 16) * 128 + ks * 32 + aByte));
            #pragma unroll
            for (int jj = 0; jj < 2; jj++)
                ldsm_x4(bf[2*jj][0], bf[2*jj][1], bf[2*jj+1][0], bf[2*jj+1][1],
                        st + OFF_B + swz((bRow + jj * 16) * 128 + ks * 32 + bByte));
            // hi pass: a_hi * b -> f32 acc
            #pragma unroll
            for (int i = 0; i < 4; i++)
                #pragma unroll
                for (int j = 0; j < 4; j++)
                    mma_f16(acc[i][j][0], acc[i][j][1], acc[i][j][2], acc[i][j][3],
                            af[i][0], af[i][1], af[i][2], af[i][3], bf[j][0], bf[j][1]);
            // lo pass: a_lo * b -> f16 acc
            if (NPASS == 2) {
                uint32_t al[4][4];
                #pragma unroll
                for (int i = 0; i < 4; i++)
                    ldsm_x4(al[i][0], al[i][1], al[i][2], al[i][3],
                            st + OFF_ALO + swz((aRow + i * 16) * 128 + ks * 32 + aByte));
                #pragma unroll
                for (int i = 0; i < 4; i++)
                    #pragma unroll
                    for (int j = 0; j < 4; j++)
                        mma_f16acc(accl[i][j][0], accl[i][j][1],
                                   al[i][0], al[i][1], al[i][2], al[i][3],
                                   bf[j][0], bf[j][1]);
            }
        }
        __syncthreads();
    }

    // epilogue
    const int erow = rowBase + warp_m * 64 + (lane >> 2);
    const int ecol = colBase + warp_n * 32 + (lane & 3) * 2;
    #pragma unroll
    for (int i = 0; i < 4; i++) {
        #pragma unroll
        for (int j = 0; j < 4; j++) {
            int col = ecol + j * 8;
            float b0 = bias[col], b1 = bias[col + 1];
            #pragma unroll
            for (int h = 0; h < 2; h++) {
                int r = erow + i * 16 + h * 8;
                float x0 = acc[i][j][2 * h + 0] + b0;
                float x1 = acc[i][j][2 * h + 1] + b1;
                if (NPASS == 2) {
                    __half2 lv = *(__half2*)&accl[i][j][h];
                    x0 += __low2float(lv);
                    x1 += __high2float(lv);
                }
                x0 = epi_act<EPI>(x0);
                x1 = epi_act<EPI>(x1);
                if (SPLIT == 0) {
                    *(float2*)(outF + (size_t)r * N + col) = make_float2(x0, x1);
                } else {
                    uint32_t hp, lp;
                    split2h(x0, x1, hp, lp);
                    *(uint32_t*)(oHi + (size_t)r * N + col) = hp;
                    *(uint32_t*)(oLo + (size_t)r * N + col) = lp;
                }
            }
        }
    }
}

// ---------------------------------------------------------------------------
// Launch
// ---------------------------------------------------------------------------
extern "C" void kernel_launch(void* const* d_in, const int* in_sizes, int n_in,
                              void* d_out, int out_size) {
    (void)in_sizes; (void)n_in; (void)out_size;

    const int*   ids  = (const int*)d_in[0];
    const float* tbl  = (const float*)d_in[1];
    const float* en_g = (const float*)d_in[2];
    const float* en_b = (const float*)d_in[3];
    const float* wA[2] = {(const float*)d_in[4],  (const float*)d_in[8]};
    const float* bA[2] = {(const float*)d_in[5],  (const float*)d_in[9]};
    const float* wB[2] = {(const float*)d_in[6],  (const float*)d_in[10]};
    const float* bB[2] = {(const float*)d_in[7],  (const float*)d_in[11]};
    const float* dw0 = (const float*)d_in[12];
    const float* db0 = (const float*)d_in[13];
    const float* fw0 = (const float*)d_in[14];
    const float* fb0 = (const float*)d_in[15];
    const float* iw0 = (const float*)d_in[16];
    const float* ib0 = (const float*)d_in[17];
    const float* cg0 = (const float*)d_in[18];
    const float* cb0 = (const float*)d_in[19];
    const float* ow = (const float*)d_in[28];
    const float* ob = (const float*)d_in[29];
    float* out = (float*)d_out;

    float *pdl, *pfg, *pig;
    __half *aHi[2], *aLo[2], *wt;
    cudaGetSymbolAddress((void**)&pdl,   g_dl);
    cudaGetSymbolAddress((void**)&pfg,   g_fg);
    cudaGetSymbolAddress((void**)&pig,   g_ig);
    cudaGetSymbolAddress((void**)&aHi[0], g_act_hi0);
    cudaGetSymbolAddress((void**)&aLo[0], g_act_lo0);
    cudaGetSymbolAddress((void**)&aHi[1], g_act_hi1);
    cudaGetSymbolAddress((void**)&aLo[1], g_act_lo1);
    cudaGetSymbolAddress((void**)&wt,    g_wt);

    cudaFuncSetAttribute(gemm_f16<1, 1, 2>, cudaFuncAttributeMaxDynamicSharedMemorySize, GEMM_SMEM);
    cudaFuncSetAttribute(gemm_f16<2, 0, 1>, cudaFuncAttributeMaxDynamicSharedMemorySize, GEMM_SMEM);
    cudaFuncSetAttribute(gemm_f16<3, 0, 1>, cudaFuncAttributeMaxDynamicSharedMemorySize, GEMM_SMEM);
    cudaFuncSetAttribute(gemm_f16<0, 0, 2>, cudaFuncAttributeMaxDynamicSharedMemorySize, GEMM_SMEM);

    // weight arena offsets (elements): wA0 wB0 dw0 fw0 iw0 wA1 wB1 ow
    const long long EO_WA[2] = {0, 37748736};
    const long long EO_WB[2] = {8388608, 46137344};
    const long long EO_DW = 25165824, EO_FW = 29360128, EO_IW = 33554432;
    const long long EO_OW = 62914560;

    {
        WJobs jobs;
        const float* ws[NJOB] = {wA[0], wB[0], dw0, fw0, iw0, wA[1], wB[1], ow};
        const long long eo[NJOB] = {EO_WA[0], EO_WB[0], EO_DW, EO_FW, EO_IW,
                                    EO_WA[1], EO_WB[1], EO_OW};
        const int Ks[NJOB] = {2048, 4096, 4096, 4096, 4096, 2048, 4096, 4096};
        const int Ns[NJOB] = {4096, 4096, 1024, 1024, 1024, 4096, 4096, 32000};
        int cum = 0;
        for (int j = 0; j < NJOB; j++) {
            jobs.W[j] = ws[j]; jobs.off[j] = eo[j];
            jobs.K[j] = Ks[j]; jobs.N[j] = Ns[j];
            jobs.start[j] = cum;
            cum += (Ns[j] >> 5) * (Ks[j] >> 5);
        }
        jobs.start[NJOB] = cum;
        wsplit_all_kernel<<<cum, 256>>>(jobs, wt);
    }

    embed_ln_kernel<<<NTOK, 256>>>(ids, tbl, en_g, en_b);

    for (int blk = 0; blk < 2; blk++) {
        int p = blk & 1;
        int q = 1 - p;
        cat_split_kernel<<<NTOK * 2048 / 4 / 256, 256>>>(blk == 0 ? 1 : 0, aHi[p], aLo[p]);
        // h1 = relu(cat @ wA + bA) -> split buffers
        gemm_f16<1, 1, 2><<<dim3(NTOK / 128, HDIM / 128), 256, GEMM_SMEM>>>(
            aHi[p], aLo[p], wt + EO_WA[blk], bA[blk],
            nullptr, aHi[q], aLo[q], HDIM, EDIM + CDIM);
        // h2 = relu(h1 @ wB + bB) -> split buffers
        gemm_f16<1, 1, 2><<<dim3(NTOK / 128, HDIM / 128), 256, GEMM_SMEM>>>(
            aHi[q], aLo[q], wt + EO_WB[blk], bB[blk],
            nullptr, aHi[p], aLo[p], HDIM, HDIM);
        if (blk == 0) {
            // gates: single-pass fp16 (error absorbed by sigmoid/tanh + LN)
            gemm_f16<2, 0, 1><<<dim3(NTOK / 128, CDIM / 128), 256, GEMM_SMEM>>>(
                aHi[p], nullptr, wt + EO_DW, db0, pdl, nullptr, nullptr, CDIM, HDIM);
            gemm_f16<3, 0, 1><<<dim3(NTOK / 128, CDIM / 128), 256, GEMM_SMEM>>>(
                aHi[p], nullptr, wt + EO_IW, ib0, pig, nullptr, nullptr, CDIM, HDIM);
            // f-gate not needed: ctx starts at zero, f*0 = 0. (fw/fb dead for blk0.)
            (void)fw0; (void)fb0; (void)pfg;
            ctx_update_kernel<<<NTOK, 256>>>(cg0, cb0);
        }
    }

    // logits = h2(block 1) @ ow + ob   (h2 of block 1 in parity-1 buffers)
    gemm_f16<0, 0, 2><<<dim3(NTOK / 128, VDIM / 128), 256, GEMM_SMEM>>>(
        aHi[1], aLo[1], wt + EO_OW, ob,
        out, nullptr, nullptr, VDIM, HDIM);
}

// round 9
// speedup vs baseline: 4.5761x; 1.0452x over previous
#include <cuda_runtime.h>
#include <cuda_fp16.h>
#include <cstdint>
#include <math.h>

#define NTOK 4096
#define EDIM 1024
#define CDIM 1024
#define HDIM 4096
#define VDIM 32000
#define EPS_LN 1e-5f

// ---------------------------------------------------------------------------
// Static scratch
// ---------------------------------------------------------------------------
__device__ float g_x[NTOK * EDIM];
__device__ float g_ctx[NTOK * CDIM];
__device__ float g_dl[NTOK * CDIM];
__device__ float g_ig[NTOK * CDIM];

// activation ping-pong buffers, split hi/lo fp16
__device__ __half g_act_hi0[NTOK * HDIM];
__device__ __half g_act_lo0[NTOK * HDIM];
__device__ __half g_act_hi1[NTOK * HDIM];
__device__ __half g_act_lo1[NTOK * HDIM];

// transposed weights [N,K], single fp16 limb (8 live jobs)
#define WT_TOTAL 193986560ULL
__device__ __half g_wt[WT_TOTAL];

// ---------------------------------------------------------------------------
// helpers
// ---------------------------------------------------------------------------
__device__ __forceinline__ uint32_t smem_to_u32(const void* p) {
    uint32_t a;
    asm("{ .reg .u64 t; cvta.to.shared.u64 t, %1; cvt.u32.u64 %0, t; }"
        : "=r"(a) : "l"(p));
    return a;
}
__device__ __forceinline__ uint32_t swz(uint32_t o) { return o ^ ((o >> 3) & 0x70); }
__device__ __forceinline__ void cp_async16(uint32_t dst, const void* src) {
    asm volatile("cp.async.cg.shared.global [%0], [%1], 16;" :: "r"(dst), "l"(src));
}
template <int N>
__device__ __forceinline__ void cp_wait() {
    asm volatile("cp.async.wait_group %0;" :: "n"(N) : "memory");
}
__device__ __forceinline__ void cp_commit() {
    asm volatile("cp.async.commit_group;" ::: "memory");
}
__device__ __forceinline__ void ldsm_x4(uint32_t& a0, uint32_t& a1, uint32_t& a2,
                                        uint32_t& a3, uint32_t addr) {
    asm volatile("ldmatrix.sync.aligned.m8n8.x4.shared.b16 {%0,%1,%2,%3}, [%4];"
                 : "=r"(a0), "=r"(a1), "=r"(a2), "=r"(a3) : "r"(addr));
}
__device__ __forceinline__ void ldsm_x2(uint32_t& a0, uint32_t& a1, uint32_t addr) {
    asm volatile("ldmatrix.sync.aligned.m8n8.x2.shared.b16 {%0,%1}, [%2];"
                 : "=r"(a0), "=r"(a1) : "r"(addr));
}
// fp16 MMA, fp32 accumulators
__device__ __forceinline__ void mma_f16(float& d0, float& d1, float& d2, float& d3,
                                        uint32_t a0, uint32_t a1, uint32_t a2, uint32_t a3,
                                        uint32_t b0, uint32_t b1) {
    asm volatile(
        "mma.sync.aligned.m16n8k16.row.col.f32.f16.f16.f32 "
        "{%0,%1,%2,%3}, {%4,%5,%6,%7}, {%8,%9}, {%0,%1,%2,%3};"
        : "+f"(d0), "+f"(d1), "+f"(d2), "+f"(d3)
        : "r"(a0), "r"(a1), "r"(a2), "r"(a3), "r"(b0), "r"(b1));
}

// ---------------------------------------------------------------------------
// block reductions (256 threads)
// ---------------------------------------------------------------------------
__device__ __forceinline__ float block_sum256(float val) {
    __shared__ float sh[8];
    int lane = threadIdx.x & 31;
    #pragma unroll
    for (int o = 16; o > 0; o >>= 1) val += __shfl_xor_sync(0xffffffffu, val, o);
    if (lane == 0) sh[threadIdx.x >> 5] = val;
    __syncthreads();
    float t = (lane < 8) ? sh[lane] : 0.f;
    #pragma unroll
    for (int o = 4; o > 0; o >>= 1) t += __shfl_xor_sync(0xffffffffu, t, o);
    t = __shfl_sync(0xffffffffu, t, 0);
    __syncthreads();
    return t;
}

// ---------------------------------------------------------------------------
// small kernels
// ---------------------------------------------------------------------------
__global__ void embed_ln_kernel(const int* __restrict__ ids,
                                const float* __restrict__ tbl,
                                const float* __restrict__ gw,
                                const float* __restrict__ gb) {
    int row = blockIdx.x;
    size_t base = (size_t)ids[row] * EDIM;
    float v[4];
    float s = 0.f;
    #pragma unroll
    for (int i = 0; i < 4; i++) { v[i] = tbl[base + threadIdx.x + i * 256]; s += v[i]; }
    float mean = block_sum256(s) * (1.f / (float)EDIM);
    float s2 = 0.f;
    #pragma unroll
    for (int i = 0; i < 4; i++) { float d = v[i] - mean; s2 += d * d; }
    float rstd = rsqrtf(block_sum256(s2) * (1.f / (float)EDIM) + EPS_LN);
    #pragma unroll
    for (int i = 0; i < 4; i++) {
        int c = threadIdx.x + i * 256;
        g_x[(size_t)row * EDIM + c] = (v[i] - mean) * rstd * gw[c] + gb[c];
    }
}

// ctx = LN(i*delta) for block 0 (ctx starts at zero -> f-gate term vanishes)
__global__ void ctx_update_kernel(const float* __restrict__ cg,
                                  const float* __restrict__ cb) {
    int row = blockIdx.x;
    size_t b = (size_t)row * CDIM;
    float v[4];
    float s = 0.f;
    #pragma unroll
    for (int i = 0; i < 4; i++) {
        int c = threadIdx.x + i * 256;
        v[i] = g_ig[b + c] * g_dl[b + c];
        s += v[i];
    }
    float mean = block_sum256(s) * (1.f / (float)CDIM);
    float s2 = 0.f;
    #pragma unroll
    for (int i = 0; i < 4; i++) { float d = v[i] - mean; s2 += d * d; }
    float rstd = rsqrtf(block_sum256(s2) * (1.f / (float)CDIM) + EPS_LN);
    #pragma unroll
    for (int i = 0; i < 4; i++) {
        int c = threadIdx.x + i * 256;
        g_ctx[b + c] = (v[i] - mean) * rstd * cg[c] + cb[c];
    }
}

__device__ __forceinline__ void split2h(float x0, float x1, uint32_t& hp, uint32_t& lp) {
    __half h0 = __float2half(x0), h1 = __float2half(x1);
    __half l0 = __float2half(x0 - __half2float(h0));
    __half l1 = __float2half(x1 - __half2float(h1));
    __half2 hh; hh.x = h0; hh.y = h1;
    __half2 ll; ll.x = l0; ll.y = l1;
    hp = *(uint32_t*)&hh; lp = *(uint32_t*)&ll;
}

// cat = [x | (first ? 0 : ctx)] -> hi/lo fp16, row stride 2048
__global__ void cat_split_kernel(int first, __half* __restrict__ hi,
                                 __half* __restrict__ lo) {
    int idx = blockIdx.x * blockDim.x + threadIdx.x;
    int row = idx >> 9, c4 = idx & 511;
    float4 v;
    if (c4 < 256)      v = ((const float4*)g_x)[row * 256 + c4];
    else if (first)    v = make_float4(0.f, 0.f, 0.f, 0.f);
    else               v = ((const float4*)g_ctx)[row * 256 + (c4 - 256)];
    uint32_t hp0, lp0, hp1, lp1;
    split2h(v.x, v.y, hp0, lp0);
    split2h(v.z, v.w, hp1, lp1);
    *(uint2*)(hi + (size_t)row * 2048 + c4 * 4) = make_uint2(hp0, hp1);
    *(uint2*)(lo + (size_t)row * 2048 + c4 * 4) = make_uint2(lp0, lp1);
}

// ---------------------------------------------------------------------------
// Fused weight conversion: 8 live jobs, W[K,N] fp32 -> Wt[N,K] fp16
// ---------------------------------------------------------------------------
#define NJOB 8
struct WJobs {
    const float* W[NJOB];
    long long off[NJOB];
    int K[NJOB];
    int N[NJOB];
    int start[NJOB + 1];
};

__global__ void wsplit_all_kernel(WJobs jobs, __half* __restrict__ T) {
    __shared__ float t[32][33];
    int b = blockIdx.x;
    int ji = 0;
    #pragma unroll
    for (int j = 0; j < NJOB; j++) if (b >= jobs.start[j + 1]) ji = j + 1;
    const float* W = jobs.W[ji];
    const int K = jobs.K[ji], N = jobs.N[ji];
    const long long off = jobs.off[ji];
    int tno = b - jobs.start[ji];
    int ntiles = N >> 5;
    int n0 = (tno % ntiles) << 5, k0 = (tno / ntiles) << 5;
    int tx = threadIdx.x & 31, ty = threadIdx.x >> 5;
    #pragma unroll
    for (int i = 0; i < 4; i++) {
        int kk = ty + i * 8;
        t[kk][tx] = W[(size_t)(k0 + kk) * N + n0 + tx];
    }
    __syncthreads();
    #pragma unroll
    for (int i = 0; i < 4; i++) {
        int nn = ty + i * 8;
        T[(size_t)off + (size_t)(n0 + nn) * K + k0 + tx] = __float2half(t[tx][nn]);
    }
}

// ---------------------------------------------------------------------------
// fp16 GEMM: C[M,N] = act(A @ W^T + bias)
// A split hi/lo fp16 [M,K]; W single fp16 limb [N,K].
// Block tile 128x256, BK=64. 512 threads = 16 warps (4x4), warp tile 32x64.
// NPASS=2: hi + lo passes, both into fp32 acc. NPASS=1: hi only (gates).
// Stage: Ahi(16K)|Alo(16K)|B(32K) = 64KB; 3-stage pipeline = 192KB smem.
// ---------------------------------------------------------------------------
#define STAGE_BYTES 65536
#define OFF_ALO 16384
#define OFF_B 32768
#define GEMM_SMEM (3 * STAGE_BYTES)

template <int EPI>
__device__ __forceinline__ float epi_act(float x) {
    if (EPI == 1) return fmaxf(x, 0.f);
    if (EPI == 2) return tanhf(x);
    if (EPI == 3) return 1.f / (1.f + expf(-x));
    return x;
}

template <int EPI, int SPLIT, int NPASS>
__global__ void __launch_bounds__(512, 1)
gemm_f16(const __half* __restrict__ aHi, const __half* __restrict__ aLo,
         const __half* __restrict__ bW,
         const float* __restrict__ bias,
         float* __restrict__ outF,
         __half* __restrict__ oHi, __half* __restrict__ oLo,
         int N, int K) {
    extern __shared__ char smem[];
    const uint32_t sbase = smem_to_u32(smem);
    const int tid = threadIdx.x, wid = tid >> 5, lane = tid & 31;
    const int warp_m = wid & 3, warp_n = wid >> 2;     // 4x4 warps
    const int rowBase = blockIdx.x * 128;
    const int colBase = blockIdx.y * 256;

    float acc[2][8][4];
    #pragma unroll
    for (int i = 0; i < 2; i++)
        #pragma unroll
        for (int j = 0; j < 8; j++)
            #pragma unroll
            for (int u = 0; u < 4; u++) acc[i][j][u] = 0.f;

    const int nk = K >> 6;

    // ldmatrix lane addressing
    const int aRow = warp_m * 32 + (lane & 15);                      // + i*16
    const int aByte = (lane >> 4) << 4;                              // 0/16
    const int bRow = warp_n * 64 + ((lane >> 4) << 3) + (lane & 7);  // + jj*16
    const int bByte = ((lane >> 3) & 1) << 4;                        // 0/16

    auto fill = [&](int kt) {
        const uint32_t st = sbase + (kt % 3) * STAGE_BYTES;
        const int k0 = kt << 6;
        const int chunks = (NPASS == 2) ? 8 : 6;
        #pragma unroll
        for (int i = 0; i < chunks; i++) {
            int o = tid + (i << 9);
            const __half* src;
            uint32_t dst;
            if (NPASS == 2) {
                if (o < 1024) {
                    int r = o >> 3, c = o & 7;
                    src = aHi + (size_t)(rowBase + r) * K + k0 + c * 8;
                    dst = st + swz(r * 128 + c * 16);
                } else if (o < 2048) {
                    int q = o - 1024, r = q >> 3, c = q & 7;
                    src = aLo + (size_t)(rowBase + r) * K + k0 + c * 8;
                    dst = st + OFF_ALO + swz(r * 128 + c * 16);
                } else {
                    int q = o - 2048, r = q >> 3, c = q & 7;
                    src = bW + (size_t)(colBase + r) * K + k0 + c * 8;
                    dst = st + OFF_B + swz(r * 128 + c * 16);
                }
            } else {
                if (o < 1024) {
                    int r = o >> 3, c = o & 7;
                    src = aHi + (size_t)(rowBase + r) * K + k0 + c * 8;
                    dst = st + swz(r * 128 + c * 16);
                } else {
                    int q = o - 1024, r = q >> 3, c = q & 7;
                    src = bW + (size_t)(colBase + r) * K + k0 + c * 8;
                    dst = st + OFF_B + swz(r * 128 + c * 16);
                }
            }
            cp_async16(dst, src);
        }
        cp_commit();
    };

    fill(0);
    fill(1);
    for (int kt = 0; kt < nk; kt++) {
        if (kt + 1 < nk) cp_wait<1>();
        else             cp_wait<0>();
        __syncthreads();
        if (kt + 2 < nk) fill(kt + 2);

        const uint32_t st = sbase + (kt % 3) * STAGE_BYTES;
        #pragma unroll
        for (int ks = 0; ks < 4; ks++) {
            uint32_t af[2][4], bf[8][2];
            #pragma unroll
            for (int i = 0; i < 2; i++)
                ldsm_x4(af[i][0], af[i][1], af[i][2], af[i][3],
                        st + swz((aRow + i * 16) * 128 + ks * 32 + aByte));
            #pragma unroll
            for (int jj = 0; jj < 4; jj++)
                ldsm_x4(bf[2*jj][0], bf[2*jj][1], bf[2*jj+1][0], bf[2*jj+1][1],
                        st + OFF_B + swz((bRow + jj * 16) * 128 + ks * 32 + bByte));
            // hi pass
            #pragma unroll
            for (int i = 0; i < 2; i++)
                #pragma unroll
                for (int j = 0; j < 8; j++)
                    mma_f16(acc[i][j][0], acc[i][j][1], acc[i][j][2], acc[i][j][3],
                            af[i][0], af[i][1], af[i][2], af[i][3], bf[j][0], bf[j][1]);
            // lo pass (same fp32 accumulators)
            if (NPASS == 2) {
                uint32_t al[2][4];
                #pragma unroll
                for (int i = 0; i < 2; i++)
                    ldsm_x4(al[i][0], al[i][1], al[i][2], al[i][3],
                            st + OFF_ALO + swz((aRow + i * 16) * 128 + ks * 32 + aByte));
                #pragma unroll
                for (int i = 0; i < 2; i++)
                    #pragma unroll
                    for (int j = 0; j < 8; j++)
                        mma_f16(acc[i][j][0], acc[i][j][1], acc[i][j][2], acc[i][j][3],
                                al[i][0], al[i][1], al[i][2], al[i][3], bf[j][0], bf[j][1]);
            }
        }
        __syncthreads();
    }

    // epilogue
    const int erow = rowBase + warp_m * 32 + (lane >> 2);
    const int ecol = colBase + warp_n * 64 + (lane & 3) * 2;
    #pragma unroll
    for (int i = 0; i < 2; i++) {
        #pragma unroll
        for (int j = 0; j < 8; j++) {
            int col = ecol + j * 8;
            float b0 = bias[col], b1 = bias[col + 1];
            #pragma unroll
            for (int h = 0; h < 2; h++) {
                int r = erow + i * 16 + h * 8;
                float x0 = epi_act<EPI>(acc[i][j][2 * h + 0] + b0);
                float x1 = epi_act<EPI>(acc[i][j][2 * h + 1] + b1);
                if (SPLIT == 0) {
                    *(float2*)(outF + (size_t)r * N + col) = make_float2(x0, x1);
                } else {
                    uint32_t hp, lp;
                    split2h(x0, x1, hp, lp);
                    *(uint32_t*)(oHi + (size_t)r * N + col) = hp;
                    *(uint32_t*)(oLo + (size_t)r * N + col) = lp;
                }
            }
        }
    }
}

// ---------------------------------------------------------------------------
// Launch
// ---------------------------------------------------------------------------
extern "C" void kernel_launch(void* const* d_in, const int* in_sizes, int n_in,
                              void* d_out, int out_size) {
    (void)in_sizes; (void)n_in; (void)out_size;

    const int*   ids  = (const int*)d_in[0];
    const float* tbl  = (const float*)d_in[1];
    const float* en_g = (const float*)d_in[2];
    const float* en_b = (const float*)d_in[3];
    const float* wA[2] = {(const float*)d_in[4],  (const float*)d_in[8]};
    const float* bA[2] = {(const float*)d_in[5],  (const float*)d_in[9]};
    const float* wB[2] = {(const float*)d_in[6],  (const float*)d_in[10]};
    const float* bB[2] = {(const float*)d_in[7],  (const float*)d_in[11]};
    const float* dw0 = (const float*)d_in[12];
    const float* db0 = (const float*)d_in[13];
    const float* fw0 = (const float*)d_in[14];
    const float* fb0 = (const float*)d_in[15];
    const float* iw0 = (const float*)d_in[16];
    const float* ib0 = (const float*)d_in[17];
    const float* cg0 = (const float*)d_in[18];
    const float* cb0 = (const float*)d_in[19];
    const float* ow = (const float*)d_in[28];
    const float* ob = (const float*)d_in[29];
    float* out = (float*)d_out;

    float *pdl, *pig;
    __half *aHi[2], *aLo[2], *wt;
    cudaGetSymbolAddress((void**)&pdl,   g_dl);
    cudaGetSymbolAddress((void**)&pig,   g_ig);
    cudaGetSymbolAddress((void**)&aHi[0], g_act_hi0);
    cudaGetSymbolAddress((void**)&aLo[0], g_act_lo0);
    cudaGetSymbolAddress((void**)&aHi[1], g_act_hi1);
    cudaGetSymbolAddress((void**)&aLo[1], g_act_lo1);
    cudaGetSymbolAddress((void**)&wt,    g_wt);

    cudaFuncSetAttribute(gemm_f16<1, 1, 2>, cudaFuncAttributeMaxDynamicSharedMemorySize, GEMM_SMEM);
    cudaFuncSetAttribute(gemm_f16<2, 0, 1>, cudaFuncAttributeMaxDynamicSharedMemorySize, GEMM_SMEM);
    cudaFuncSetAttribute(gemm_f16<3, 0, 1>, cudaFuncAttributeMaxDynamicSharedMemorySize, GEMM_SMEM);
    cudaFuncSetAttribute(gemm_f16<0, 0, 2>, cudaFuncAttributeMaxDynamicSharedMemorySize, GEMM_SMEM);

    // weight arena offsets (elements): wA0 wB0 dw0 fw0 iw0 wA1 wB1 ow
    const long long EO_WA[2] = {0, 37748736};
    const long long EO_WB[2] = {8388608, 46137344};
    const long long EO_DW = 25165824, EO_FW = 29360128, EO_IW = 33554432;
    const long long EO_OW = 62914560;

    {
        WJobs jobs;
        const float* ws[NJOB] = {wA[0], wB[0], dw0, fw0, iw0, wA[1], wB[1], ow};
        const long long eo[NJOB] = {EO_WA[0], EO_WB[0], EO_DW, EO_FW, EO_IW,
                                    EO_WA[1], EO_WB[1], EO_OW};
        const int Ks[NJOB] = {2048, 4096, 4096, 4096, 4096, 2048, 4096, 4096};
        const int Ns[NJOB] = {4096, 4096, 1024, 1024, 1024, 4096, 4096, 32000};
        int cum = 0;
        for (int j = 0; j < NJOB; j++) {
            jobs.W[j] = ws[j]; jobs.off[j] = eo[j];
            jobs.K[j] = Ks[j]; jobs.N[j] = Ns[j];
            jobs.start[j] = cum;
            cum += (Ns[j] >> 5) * (Ks[j] >> 5);
        }
        jobs.start[NJOB] = cum;
        wsplit_all_kernel<<<cum, 256>>>(jobs, wt);
    }

    embed_ln_kernel<<<NTOK, 256>>>(ids, tbl, en_g, en_b);

    for (int blk = 0; blk < 2; blk++) {
        int p = blk & 1;
        int q = 1 - p;
        cat_split_kernel<<<NTOK * 2048 / 4 / 256, 256>>>(blk == 0 ? 1 : 0, aHi[p], aLo[p]);
        // h1 = relu(cat @ wA + bA) -> split buffers
        gemm_f16<1, 1, 2><<<dim3(NTOK / 128, HDIM / 256), 512, GEMM_SMEM>>>(
            aHi[p], aLo[p], wt + EO_WA[blk], bA[blk],
            nullptr, aHi[q], aLo[q], HDIM, EDIM + CDIM);
        // h2 = relu(h1 @ wB + bB) -> split buffers
        gemm_f16<1, 1, 2><<<dim3(NTOK / 128, HDIM / 256), 512, GEMM_SMEM>>>(
            aHi[q], aLo[q], wt + EO_WB[blk], bB[blk],
            nullptr, aHi[p], aLo[p], HDIM, HDIM);
        if (blk == 0) {
            // gates: single-pass fp16 (error absorbed by tanh/sigmoid + LN);
            // f-gate dead (ctx starts at zero)
            gemm_f16<2, 0, 1><<<dim3(NTOK / 128, CDIM / 256), 512, GEMM_SMEM>>>(
                aHi[p], nullptr, wt + EO_DW, db0, pdl, nullptr, nullptr, CDIM, HDIM);
            gemm_f16<3, 0, 1><<<dim3(NTOK / 128, CDIM / 256), 512, GEMM_SMEM>>>(
                aHi[p], nullptr, wt + EO_IW, ib0, pig, nullptr, nullptr, CDIM, HDIM);
            (void)fw0; (void)fb0;
            ctx_update_kernel<<<NTOK, 256>>>(cg0, cb0);
        }
    }

    // logits = h2(block 1) @ ow + ob   (h2 of block 1 in parity-1 buffers)
    gemm_f16<0, 0, 2><<<dim3(NTOK / 128, VDIM / 256), 512, GEMM_SMEM>>>(
        aHi[1], aLo[1], wt + EO_OW, ob,
        out, nullptr, nullptr, VDIM, HDIM);
}

// round 10
// speedup vs baseline: 6.5398x; 1.4291x over previous
#include <cuda_runtime.h>
#include <cuda_fp16.h>
#include <cstdint>
#include <math.h>

#define NTOK 4096
#define EDIM 1024
#define CDIM 1024
#define HDIM 4096
#define VDIM 32000
#define EPS_LN 1e-5f

// ---------------------------------------------------------------------------
// Static scratch
// ---------------------------------------------------------------------------
__device__ float g_x[NTOK * EDIM];
__device__ float g_ctx[NTOK * CDIM];
__device__ float g_dl[NTOK * CDIM];
__device__ float g_ig[NTOK * CDIM];

// activation ping-pong buffers, split hi/lo fp16
__device__ __half g_act_hi0[NTOK * HDIM];
__device__ __half g_act_lo0[NTOK * HDIM];
__device__ __half g_act_hi1[NTOK * HDIM];
__device__ __half g_act_lo1[NTOK * HDIM];

// transposed weights [N,K], single fp16 limb (8 live jobs)
#define WT_TOTAL 193986560ULL
__device__ __half g_wt[WT_TOTAL];

// ---------------------------------------------------------------------------
// helpers
// ---------------------------------------------------------------------------
__device__ __forceinline__ uint32_t smem_to_u32(const void* p) {
    uint32_t a;
    asm("{ .reg .u64 t; cvta.to.shared.u64 t, %1; cvt.u32.u64 %0, t; }"
        : "=r"(a) : "l"(p));
    return a;
}
__device__ __forceinline__ uint32_t swz(uint32_t o) { return o ^ ((o >> 3) & 0x70); }
__device__ __forceinline__ void cp_async16(uint32_t dst, const void* src) {
    asm volatile("cp.async.cg.shared.global [%0], [%1], 16;" :: "r"(dst), "l"(src));
}
template <int N>
__device__ __forceinline__ void cp_wait() {
    asm volatile("cp.async.wait_group %0;" :: "n"(N) : "memory");
}
__device__ __forceinline__ void cp_commit() {
    asm volatile("cp.async.commit_group;" ::: "memory");
}
__device__ __forceinline__ void ldsm_x4(uint32_t& a0, uint32_t& a1, uint32_t& a2,
                                        uint32_t& a3, uint32_t addr) {
    asm volatile("ldmatrix.sync.aligned.m8n8.x4.shared.b16 {%0,%1,%2,%3}, [%4];"
                 : "=r"(a0), "=r"(a1), "=r"(a2), "=r"(a3) : "r"(addr));
}
// fp16 MMA, fp32 accumulators
__device__ __forceinline__ void mma_f16(float& d0, float& d1, float& d2, float& d3,
                                        uint32_t a0, uint32_t a1, uint32_t a2, uint32_t a3,
                                        uint32_t b0, uint32_t b1) {
    asm volatile(
        "mma.sync.aligned.m16n8k16.row.col.f32.f16.f16.f32 "
        "{%0,%1,%2,%3}, {%4,%5,%6,%7}, {%8,%9}, {%0,%1,%2,%3};"
        : "+f"(d0), "+f"(d1), "+f"(d2), "+f"(d3)
        : "r"(a0), "r"(a1), "r"(a2), "r"(a3), "r"(b0), "r"(b1));
}

// ---------------------------------------------------------------------------
// block reductions (256 threads)
// ---------------------------------------------------------------------------
__device__ __forceinline__ float block_sum256(float val) {
    __shared__ float sh[8];
    int lane = threadIdx.x & 31;
    #pragma unroll
    for (int o = 16; o > 0; o >>= 1) val += __shfl_xor_sync(0xffffffffu, val, o);
    if (lane == 0) sh[threadIdx.x >> 5] = val;
    __syncthreads();
    float t = (lane < 8) ? sh[lane] : 0.f;
    #pragma unroll
    for (int o = 4; o > 0; o >>= 1) t += __shfl_xor_sync(0xffffffffu, t, o);
    t = __shfl_sync(0xffffffffu, t, 0);
    __syncthreads();
    return t;
}

// ---------------------------------------------------------------------------
// small kernels
// ---------------------------------------------------------------------------
__global__ void embed_ln_kernel(const int* __restrict__ ids,
                                const float* __restrict__ tbl,
                                const float* __restrict__ gw,
                                const float* __restrict__ gb) {
    int row = blockIdx.x;
    size_t base = (size_t)ids[row] * EDIM;
    float v[4];
    float s = 0.f;
    #pragma unroll
    for (int i = 0; i < 4; i++) { v[i] = tbl[base + threadIdx.x + i * 256]; s += v[i]; }
    float mean = block_sum256(s) * (1.f / (float)EDIM);
    float s2 = 0.f;
    #pragma unroll
    for (int i = 0; i < 4; i++) { float d = v[i] - mean; s2 += d * d; }
    float rstd = rsqrtf(block_sum256(s2) * (1.f / (float)EDIM) + EPS_LN);
    #pragma unroll
    for (int i = 0; i < 4; i++) {
        int c = threadIdx.x + i * 256;
        g_x[(size_t)row * EDIM + c] = (v[i] - mean) * rstd * gw[c] + gb[c];
    }
}

// ctx = LN(i*delta) for block 0 (ctx starts at zero -> f-gate term vanishes)
__global__ void ctx_update_kernel(const float* __restrict__ cg,
                                  const float* __restrict__ cb) {
    int row = blockIdx.x;
    size_t b = (size_t)row * CDIM;
    float v[4];
    float s = 0.f;
    #pragma unroll
    for (int i = 0; i < 4; i++) {
        int c = threadIdx.x + i * 256;
        v[i] = g_ig[b + c] * g_dl[b + c];
        s += v[i];
    }
    float mean = block_sum256(s) * (1.f / (float)CDIM);
    float s2 = 0.f;
    #pragma unroll
    for (int i = 0; i < 4; i++) { float d = v[i] - mean; s2 += d * d; }
    float rstd = rsqrtf(block_sum256(s2) * (1.f / (float)CDIM) + EPS_LN);
    #pragma unroll
    for (int i = 0; i < 4; i++) {
        int c = threadIdx.x + i * 256;
        g_ctx[b + c] = (v[i] - mean) * rstd * cg[c] + cb[c];
    }
}

__device__ __forceinline__ void split2h(float x0, float x1, uint32_t& hp, uint32_t& lp) {
    __half h0 = __float2half(x0), h1 = __float2half(x1);
    __half l0 = __float2half(x0 - __half2float(h0));
    __half l1 = __float2half(x1 - __half2float(h1));
    __half2 hh; hh.x = h0; hh.y = h1;
    __half2 ll; ll.x = l0; ll.y = l1;
    hp = *(uint32_t*)&hh; lp = *(uint32_t*)&ll;
}

// cat = [x | (first ? 0 : ctx)] -> hi/lo fp16, row stride 2048
__global__ void cat_split_kernel(int first, __half* __restrict__ hi,
                                 __half* __restrict__ lo) {
    int idx = blockIdx.x * blockDim.x + threadIdx.x;
    int row = idx >> 9, c4 = idx & 511;
    float4 v;
    if (c4 < 256)      v = ((const float4*)g_x)[row * 256 + c4];
    else if (first)    v = make_float4(0.f, 0.f, 0.f, 0.f);
    else               v = ((const float4*)g_ctx)[row * 256 + (c4 - 256)];
    uint32_t hp0, lp0, hp1, lp1;
    split2h(v.x, v.y, hp0, lp0);
    split2h(v.z, v.w, hp1, lp1);
    *(uint2*)(hi + (size_t)row * 2048 + c4 * 4) = make_uint2(hp0, hp1);
    *(uint2*)(lo + (size_t)row * 2048 + c4 * 4) = make_uint2(lp0, lp1);
}

// ---------------------------------------------------------------------------
// Fused weight conversion: 8 live jobs, W[K,N] fp32 -> Wt[N,K] fp16
// ---------------------------------------------------------------------------
#define NJOB 8
struct WJobs {
    const float* W[NJOB];
    long long off[NJOB];
    int K[NJOB];
    int N[NJOB];
    int start[NJOB + 1];
};

__global__ void wsplit_all_kernel(WJobs jobs, __half* __restrict__ T) {
    __shared__ float t[32][33];
    int b = blockIdx.x;
    int ji = 0;
    #pragma unroll
    for (int j = 0; j < NJOB; j++) if (b >= jobs.start[j + 1]) ji = j + 1;
    const float* W = jobs.W[ji];
    const int K = jobs.K[ji], N = jobs.N[ji];
    const long long off = jobs.off[ji];
    int tno = b - jobs.start[ji];
    int ntiles = N >> 5;
    int n0 = (tno % ntiles) << 5, k0 = (tno / ntiles) << 5;
    int tx = threadIdx.x & 31, ty = threadIdx.x >> 5;
    #pragma unroll
    for (int i = 0; i < 4; i++) {
        int kk = ty + i * 8;
        t[kk][tx] = W[(size_t)(k0 + kk) * N + n0 + tx];
    }
    __syncthreads();
    #pragma unroll
    for (int i = 0; i < 4; i++) {
        int nn = ty + i * 8;
        T[(size_t)off + (size_t)(n0 + nn) * K + k0 + tx] = __float2half(t[tx][nn]);
    }
}

// ---------------------------------------------------------------------------
// fp16 GEMM: C[M,N] = act(A @ W^T + bias)
// A split hi/lo fp16 [M,K]; W single fp16 limb [N,K].
// Block tile 128x256, BK=64. 512 threads = 16 warps (4x4), warp tile 32x64.
// NPASS=2: hi + lo passes, both into fp32 acc. NPASS=1: hi only.
// Stage: Ahi(16K)|Alo(16K)|B(32K) = 64KB; 3-stage pipeline = 192KB smem.
// ---------------------------------------------------------------------------
#define STAGE_BYTES 65536
#define OFF_ALO 16384
#define OFF_B 32768
#define GEMM_SMEM (3 * STAGE_BYTES)

template <int EPI>
__device__ __forceinline__ float epi_act(float x) {
    if (EPI == 1) return fmaxf(x, 0.f);
    if (EPI == 2) return tanhf(x);
    if (EPI == 3) return 1.f / (1.f + expf(-x));
    return x;
}

template <int EPI, int SPLIT, int NPASS>
__global__ void __launch_bounds__(512, 1)
gemm_f16(const __half* __restrict__ aHi, const __half* __restrict__ aLo,
         const __half* __restrict__ bW,
         const float* __restrict__ bias,
         float* __restrict__ outF,
         __half* __restrict__ oHi, __half* __restrict__ oLo,
         int N, int K) {
    extern __shared__ char smem[];
    const uint32_t sbase = smem_to_u32(smem);
    const int tid = threadIdx.x, wid = tid >> 5, lane = tid & 31;
    const int warp_m = wid & 3, warp_n = wid >> 2;     // 4x4 warps
    const int rowBase = blockIdx.x * 128;
    const int colBase = blockIdx.y * 256;

    float acc[2][8][4];
    #pragma unroll
    for (int i = 0; i < 2; i++)
        #pragma unroll
        for (int j = 0; j < 8; j++)
            #pragma unroll
            for (int u = 0; u < 4; u++) acc[i][j][u] = 0.f;

    const int nk = K >> 6;

    // ldmatrix lane addressing
    const int aRow = warp_m * 32 + (lane & 15);                      // + i*16
    const int aByte = (lane >> 4) << 4;                              // 0/16
    const int bRow = warp_n * 64 + ((lane >> 4) << 3) + (lane & 7);  // + jj*16
    const int bByte = ((lane >> 3) & 1) << 4;                        // 0/16

    auto fill = [&](int kt) {
        const uint32_t st = sbase + (kt % 3) * STAGE_BYTES;
        const int k0 = kt << 6;
        const int chunks = (NPASS == 2) ? 8 : 6;
        #pragma unroll
        for (int i = 0; i < chunks; i++) {
            int o = tid + (i << 9);
            const __half* src;
            uint32_t dst;
            if (NPASS == 2) {
                if (o < 1024) {
                    int r = o >> 3, c = o & 7;
                    src = aHi + (size_t)(rowBase + r) * K + k0 + c * 8;
                    dst = st + swz(r * 128 + c * 16);
                } else if (o < 2048) {
                    int q = o - 1024, r = q >> 3, c = q & 7;
                    src = aLo + (size_t)(rowBase + r) * K + k0 + c * 8;
                    dst = st + OFF_ALO + swz(r * 128 + c * 16);
                } else {
                    int q = o - 2048, r = q >> 3, c = q & 7;
                    src = bW + (size_t)(colBase + r) * K + k0 + c * 8;
                    dst = st + OFF_B + swz(r * 128 + c * 16);
                }
            } else {
                if (o < 1024) {
                    int r = o >> 3, c = o & 7;
                    src = aHi + (size_t)(rowBase + r) * K + k0 + c * 8;
                    dst = st + swz(r * 128 + c * 16);
                } else {
                    int q = o - 1024, r = q >> 3, c = q & 7;
                    src = bW + (size_t)(colBase + r) * K + k0 + c * 8;
                    dst = st + OFF_B + swz(r * 128 + c * 16);
                }
            }
            cp_async16(dst, src);
        }
        cp_commit();
    };

    fill(0);
    fill(1);
    for (int kt = 0; kt < nk; kt++) {
        if (kt + 1 < nk) cp_wait<1>();
        else             cp_wait<0>();
        __syncthreads();
        if (kt + 2 < nk) fill(kt + 2);

        const uint32_t st = sbase + (kt % 3) * STAGE_BYTES;
        #pragma unroll
        for (int ks = 0; ks < 4; ks++) {
            uint32_t af[2][4], bf[8][2];
            #pragma unroll
            for (int i = 0; i < 2; i++)
                ldsm_x4(af[i][0], af[i][1], af[i][2], af[i][3],
                        st + swz((aRow + i * 16) * 128 + ks * 32 + aByte));
            #pragma unroll
            for (int jj = 0; jj < 4; jj++)
                ldsm_x4(bf[2*jj][0], bf[2*jj][1], bf[2*jj+1][0], bf[2*jj+1][1],
                        st + OFF_B + swz((bRow + jj * 16) * 128 + ks * 32 + bByte));
            // hi pass
            #pragma unroll
            for (int i = 0; i < 2; i++)
                #pragma unroll
                for (int j = 0; j < 8; j++)
                    mma_f16(acc[i][j][0], acc[i][j][1], acc[i][j][2], acc[i][j][3],
                            af[i][0], af[i][1], af[i][2], af[i][3], bf[j][0], bf[j][1]);
            // lo pass (same fp32 accumulators)
            if (NPASS == 2) {
                uint32_t al[2][4];
                #pragma unroll
                for (int i = 0; i < 2; i++)
                    ldsm_x4(al[i][0], al[i][1], al[i][2], al[i][3],
                            st + OFF_ALO + swz((aRow + i * 16) * 128 + ks * 32 + aByte));
                #pragma unroll
                for (int i = 0; i < 2; i++)
                    #pragma unroll
                    for (int j = 0; j < 8; j++)
                        mma_f16(acc[i][j][0], acc[i][j][1], acc[i][j][2], acc[i][j][3],
                                al[i][0], al[i][1], al[i][2], al[i][3], bf[j][0], bf[j][1]);
            }
        }
        __syncthreads();
    }

    // epilogue
    const int erow = rowBase + warp_m * 32 + (lane >> 2);
    const int ecol = colBase + warp_n * 64 + (lane & 3) * 2;
    #pragma unroll
    for (int i = 0; i < 2; i++) {
        #pragma unroll
        for (int j = 0; j < 8; j++) {
            int col = ecol + j * 8;
            float b0 = bias[col], b1 = bias[col + 1];
            #pragma unroll
            for (int h = 0; h < 2; h++) {
                int r = erow + i * 16 + h * 8;
                float x0 = epi_act<EPI>(acc[i][j][2 * h + 0] + b0);
                float x1 = epi_act<EPI>(acc[i][j][2 * h + 1] + b1);
                if (SPLIT == 0) {
                    *(float2*)(outF + (size_t)r * N + col) = make_float2(x0, x1);
                } else {
                    uint32_t hp, lp;
                    split2h(x0, x1, hp, lp);
                    *(uint32_t*)(oHi + (size_t)r * N + col) = hp;
                    *(uint32_t*)(oLo + (size_t)r * N + col) = lp;
                }
            }
        }
    }
}

// ---------------------------------------------------------------------------
// Launch
// ---------------------------------------------------------------------------
extern "C" void kernel_launch(void* const* d_in, const int* in_sizes, int n_in,
                              void* d_out, int out_size) {
    (void)in_sizes; (void)n_in; (void)out_size;

    const int*   ids  = (const int*)d_in[0];
    const float* tbl  = (const float*)d_in[1];
    const float* en_g = (const float*)d_in[2];
    const float* en_b = (const float*)d_in[3];
    const float* wA[2] = {(const float*)d_in[4],  (const float*)d_in[8]};
    const float* bA[2] = {(const float*)d_in[5],  (const float*)d_in[9]};
    const float* wB[2] = {(const float*)d_in[6],  (const float*)d_in[10]};
    const float* bB[2] = {(const float*)d_in[7],  (const float*)d_in[11]};
    const float* dw0 = (const float*)d_in[12];
    const float* db0 = (const float*)d_in[13];
    const float* fw0 = (const float*)d_in[14];
    const float* fb0 = (const float*)d_in[15];
    const float* iw0 = (const float*)d_in[16];
    const float* ib0 = (const float*)d_in[17];
    const float* cg0 = (const float*)d_in[18];
    const float* cb0 = (const float*)d_in[19];
    const float* ow = (const float*)d_in[28];
    const float* ob = (const float*)d_in[29];
    float* out = (float*)d_out;

    float *pdl, *pig;
    __half *aHi[2], *aLo[2], *wt;
    cudaGetSymbolAddress((void**)&pdl,   g_dl);
    cudaGetSymbolAddress((void**)&pig,   g_ig);
    cudaGetSymbolAddress((void**)&aHi[0], g_act_hi0);
    cudaGetSymbolAddress((void**)&aLo[0], g_act_lo0);
    cudaGetSymbolAddress((void**)&aHi[1], g_act_hi1);
    cudaGetSymbolAddress((void**)&aLo[1], g_act_lo1);
    cudaGetSymbolAddress((void**)&wt,    g_wt);

    cudaFuncSetAttribute(gemm_f16<1, 1, 2>, cudaFuncAttributeMaxDynamicSharedMemorySize, GEMM_SMEM);
    cudaFuncSetAttribute(gemm_f16<2, 0, 1>, cudaFuncAttributeMaxDynamicSharedMemorySize, GEMM_SMEM);
    cudaFuncSetAttribute(gemm_f16<3, 0, 1>, cudaFuncAttributeMaxDynamicSharedMemorySize, GEMM_SMEM);
    cudaFuncSetAttribute(gemm_f16<0, 0, 1>, cudaFuncAttributeMaxDynamicSharedMemorySize, GEMM_SMEM);

    // weight arena offsets (elements): wA0 wB0 dw0 fw0 iw0 wA1 wB1 ow
    const long long EO_WA[2] = {0, 37748736};
    const long long EO_WB[2] = {8388608, 46137344};
    const long long EO_DW = 25165824, EO_FW = 29360128, EO_IW = 33554432;
    const long long EO_OW = 62914560;

    {
        WJobs jobs;
        const float* ws[NJOB] = {wA[0], wB[0], dw0, fw0, iw0, wA[1], wB[1], ow};
        const long long eo[NJOB] = {EO_WA[0], EO_WB[0], EO_DW, EO_FW, EO_IW,
                                    EO_WA[1], EO_WB[1], EO_OW};
        const int Ks[NJOB] = {2048, 4096, 4096, 4096, 4096, 2048, 4096, 4096};
        const int Ns[NJOB] = {4096, 4096, 1024, 1024, 1024, 4096, 4096, 32000};
        int cum = 0;
        for (int j = 0; j < NJOB; j++) {
            jobs.W[j] = ws[j]; jobs.off[j] = eo[j];
            jobs.K[j] = Ks[j]; jobs.N[j] = Ns[j];
            jobs.start[j] = cum;
            cum += (Ns[j] >> 5) * (Ks[j] >> 5);
        }
        jobs.start[NJOB] = cum;
        wsplit_all_kernel<<<cum, 256>>>(jobs, wt);
    }

    embed_ln_kernel<<<NTOK, 256>>>(ids, tbl, en_g, en_b);

    for (int blk = 0; blk < 2; blk++) {
        int p = blk & 1;
        int q = 1 - p;
        cat_split_kernel<<<NTOK * 2048 / 4 / 256, 256>>>(blk == 0 ? 1 : 0, aHi[p], aLo[p]);
        // h1 = relu(cat @ wA + bA) -> split buffers
        gemm_f16<1, 1, 2><<<dim3(NTOK / 128, HDIM / 256), 512, GEMM_SMEM>>>(
            aHi[p], aLo[p], wt + EO_WA[blk], bA[blk],
            nullptr, aHi[q], aLo[q], HDIM, EDIM + CDIM);
        // h2 = relu(h1 @ wB + bB) -> split buffers
        gemm_f16<1, 1, 2><<<dim3(NTOK / 128, HDIM / 256), 512, GEMM_SMEM>>>(
            aHi[q], aLo[q], wt + EO_WB[blk], bB[blk],
            nullptr, aHi[p], aLo[p], HDIM, HDIM);
        if (blk == 0) {
            // gates: single-pass fp16 (error absorbed by tanh/sigmoid + LN);
            // f-gate dead (ctx starts at zero)
            gemm_f16<2, 0, 1><<<dim3(NTOK / 128, CDIM / 256), 512, GEMM_SMEM>>>(
                aHi[p], nullptr, wt + EO_DW, db0, pdl, nullptr, nullptr, CDIM, HDIM);
            gemm_f16<3, 0, 1><<<dim3(NTOK / 128, CDIM / 256), 512, GEMM_SMEM>>>(
                aHi[p], nullptr, wt + EO_IW, ib0, pig, nullptr, nullptr, CDIM, HDIM);
            (void)fw0; (void)fb0;
            ctx_update_kernel<<<NTOK, 256>>>(cg0, cb0);
        }
    }

    // logits = h2(block 1) @ ow + ob — SINGLE-PASS (hi limb only).
    // The dropped lo-pass corrected only h2's fp16 quantization (~1.4e-4 RMS);
    // predicted total rel_err ~6.7e-4, under the 1e-3 gate.
    gemm_f16<0, 0, 1><<<dim3(NTOK / 128, VDIM / 256), 512, GEMM_SMEM>>>(
        aHi[1], nullptr, wt + EO_OW, ob,
        out, nullptr, nullptr, VDIM, HDIM);
}

// round 11
// speedup vs baseline: 8.2538x; 1.2621x over previous
#include <cuda_runtime.h>
#include <cuda_fp16.h>
#include <cstdint>
#include <math.h>

#define NTOK 4096
#define EDIM 1024
#define CDIM 1024
#define HDIM 4096
#define VDIM 32000
#define EPS_LN 1e-5f

// ---------------------------------------------------------------------------
// Static scratch
// ---------------------------------------------------------------------------
__device__ float g_x[NTOK * EDIM];
__device__ float g_ctx[NTOK * CDIM];
__device__ float g_dl[NTOK * CDIM];
__device__ float g_ig[NTOK * CDIM];

// activation ping-pong buffers, fp16 (single limb)
__device__ __half g_act0[NTOK * HDIM];
__device__ __half g_act1[NTOK * HDIM];

// transposed weights [N,K], single fp16 limb (8 live jobs)
#define WT_TOTAL 193986560ULL
__device__ __half g_wt[WT_TOTAL];

// ---------------------------------------------------------------------------
// helpers
// ---------------------------------------------------------------------------
__device__ __forceinline__ uint32_t smem_to_u32(const void* p) {
    uint32_t a;
    asm("{ .reg .u64 t; cvta.to.shared.u64 t, %1; cvt.u32.u64 %0, t; }"
        : "=r"(a) : "l"(p));
    return a;
}
__device__ __forceinline__ uint32_t swz(uint32_t o) { return o ^ ((o >> 3) & 0x70); }
__device__ __forceinline__ void cp_async16(uint32_t dst, const void* src) {
    asm volatile("cp.async.cg.shared.global [%0], [%1], 16;" :: "r"(dst), "l"(src));
}
template <int N>
__device__ __forceinline__ void cp_wait() {
    asm volatile("cp.async.wait_group %0;" :: "n"(N) : "memory");
}
__device__ __forceinline__ void cp_commit() {
    asm volatile("cp.async.commit_group;" ::: "memory");
}
__device__ __forceinline__ void ldsm_x4(uint32_t& a0, uint32_t& a1, uint32_t& a2,
                                        uint32_t& a3, uint32_t addr) {
    asm volatile("ldmatrix.sync.aligned.m8n8.x4.shared.b16 {%0,%1,%2,%3}, [%4];"
                 : "=r"(a0), "=r"(a1), "=r"(a2), "=r"(a3) : "r"(addr));
}
// fp16 MMA, fp32 accumulators
__device__ __forceinline__ void mma_f16(float& d0, float& d1, float& d2, float& d3,
                                        uint32_t a0, uint32_t a1, uint32_t a2, uint32_t a3,
                                        uint32_t b0, uint32_t b1) {
    asm volatile(
        "mma.sync.aligned.m16n8k16.row.col.f32.f16.f16.f32 "
        "{%0,%1,%2,%3}, {%4,%5,%6,%7}, {%8,%9}, {%0,%1,%2,%3};"
        : "+f"(d0), "+f"(d1), "+f"(d2), "+f"(d3)
        : "r"(a0), "r"(a1), "r"(a2), "r"(a3), "r"(b0), "r"(b1));
}

// ---------------------------------------------------------------------------
// block reductions (256 threads)
// ---------------------------------------------------------------------------
__device__ __forceinline__ float block_sum256(float val) {
    __shared__ float sh[8];
    int lane = threadIdx.x & 31;
    #pragma unroll
    for (int o = 16; o > 0; o >>= 1) val += __shfl_xor_sync(0xffffffffu, val, o);
    if (lane == 0) sh[threadIdx.x >> 5] = val;
    __syncthreads();
    float t = (lane < 8) ? sh[lane] : 0.f;
    #pragma unroll
    for (int o = 4; o > 0; o >>= 1) t += __shfl_xor_sync(0xffffffffu, t, o);
    t = __shfl_sync(0xffffffffu, t, 0);
    __syncthreads();
    return t;
}

// ---------------------------------------------------------------------------
// small kernels
// ---------------------------------------------------------------------------
__global__ void embed_ln_kernel(const int* __restrict__ ids,
                                const float* __restrict__ tbl,
                                const float* __restrict__ gw,
                                const float* __restrict__ gb) {
    int row = blockIdx.x;
    size_t base = (size_t)ids[row] * EDIM;
    float v[4];
    float s = 0.f;
    #pragma unroll
    for (int i = 0; i < 4; i++) { v[i] = tbl[base + threadIdx.x + i * 256]; s += v[i]; }
    float mean = block_sum256(s) * (1.f / (float)EDIM);
    float s2 = 0.f;
    #pragma unroll
    for (int i = 0; i < 4; i++) { float d = v[i] - mean; s2 += d * d; }
    float rstd = rsqrtf(block_sum256(s2) * (1.f / (float)EDIM) + EPS_LN);
    #pragma unroll
    for (int i = 0; i < 4; i++) {
        int c = threadIdx.x + i * 256;
        g_x[(size_t)row * EDIM + c] = (v[i] - mean) * rstd * gw[c] + gb[c];
    }
}

// ctx = LN(i*delta) for block 0 (ctx starts at zero -> f-gate term vanishes)
__global__ void ctx_update_kernel(const float* __restrict__ cg,
                                  const float* __restrict__ cb) {
    int row = blockIdx.x;
    size_t b = (size_t)row * CDIM;
    float v[4];
    float s = 0.f;
    #pragma unroll
    for (int i = 0; i < 4; i++) {
        int c = threadIdx.x + i * 256;
        v[i] = g_ig[b + c] * g_dl[b + c];
        s += v[i];
    }
    float mean = block_sum256(s) * (1.f / (float)CDIM);
    float s2 = 0.f;
    #pragma unroll
    for (int i = 0; i < 4; i++) { float d = v[i] - mean; s2 += d * d; }
    float rstd = rsqrtf(block_sum256(s2) * (1.f / (float)CDIM) + EPS_LN);
    #pragma unroll
    for (int i = 0; i < 4; i++) {
        int c = threadIdx.x + i * 256;
        g_ctx[b + c] = (v[i] - mean) * rstd * cg[c] + cb[c];
    }
}

// cat = [x | (first ? 0 : ctx)] -> fp16, row stride 2048
__global__ void cat_half_kernel(int first, __half* __restrict__ dst) {
    int idx = blockIdx.x * blockDim.x + threadIdx.x;
    int row = idx >> 9, c4 = idx & 511;
    float4 v;
    if (c4 < 256)      v = ((const float4*)g_x)[row * 256 + c4];
    else if (first)    v = make_float4(0.f, 0.f, 0.f, 0.f);
    else               v = ((const float4*)g_ctx)[row * 256 + (c4 - 256)];
    __half2 h0 = __floats2half2_rn(v.x, v.y);
    __half2 h1 = __floats2half2_rn(v.z, v.w);
    *(uint2*)(dst + (size_t)row * 2048 + c4 * 4) =
        make_uint2(*(uint32_t*)&h0, *(uint32_t*)&h1);
}

// ---------------------------------------------------------------------------
// Fused weight conversion: 8 live jobs, W[K,N] fp32 -> Wt[N,K] fp16
// ---------------------------------------------------------------------------
#define NJOB 8
struct WJobs {
    const float* W[NJOB];
    long long off[NJOB];
    int K[NJOB];
    int N[NJOB];
    int start[NJOB + 1];
};

__global__ void wsplit_all_kernel(WJobs jobs, __half* __restrict__ T) {
    __shared__ float t[32][33];
    int b = blockIdx.x;
    int ji = 0;
    #pragma unroll
    for (int j = 0; j < NJOB; j++) if (b >= jobs.start[j + 1]) ji = j + 1;
    const float* W = jobs.W[ji];
    const int K = jobs.K[ji], N = jobs.N[ji];
    const long long off = jobs.off[ji];
    int tno = b - jobs.start[ji];
    int ntiles = N >> 5;
    int n0 = (tno % ntiles) << 5, k0 = (tno / ntiles) << 5;
    int tx = threadIdx.x & 31, ty = threadIdx.x >> 5;
    #pragma unroll
    for (int i = 0; i < 4; i++) {
        int kk = ty + i * 8;
        t[kk][tx] = W[(size_t)(k0 + kk) * N + n0 + tx];
    }
    __syncthreads();
    #pragma unroll
    for (int i = 0; i < 4; i++) {
        int nn = ty + i * 8;
        T[(size_t)off + (size_t)(n0 + nn) * K + k0 + tx] = __float2half(t[tx][nn]);
    }
}

// ---------------------------------------------------------------------------
// fp16 GEMM (single-pass): C[M,N] = act(A @ W^T + bias)
// A fp16 [M,K]; W fp16 [N,K]. Block 128x256, BK=64.
// 512 threads = 16 warps (4x4), warp tile 32x64.
// Stage: A(16K)|B(32K) = 48KB; 3-stage pipeline = 144KB smem.
// SPLIT: 0 = fp32 out, 1 = fp16 out.
// ---------------------------------------------------------------------------
#define STAGE_BYTES 49152
#define OFF_B 16384
#define GEMM_SMEM (3 * STAGE_BYTES)

template <int EPI>
__device__ __forceinline__ float epi_act(float x) {
    if (EPI == 1) return fmaxf(x, 0.f);
    if (EPI == 2) return tanhf(x);
    if (EPI == 3) return 1.f / (1.f + expf(-x));
    return x;
}

template <int EPI, int SPLIT>
__global__ void __launch_bounds__(512, 1)
gemm_f16(const __half* __restrict__ aIn, const __half* __restrict__ bW,
         const float* __restrict__ bias,
         float* __restrict__ outF, __half* __restrict__ outH,
         int N, int K) {
    extern __shared__ char smem[];
    const uint32_t sbase = smem_to_u32(smem);
    const int tid = threadIdx.x, wid = tid >> 5, lane = tid & 31;
    const int warp_m = wid & 3, warp_n = wid >> 2;     // 4x4 warps
    const int rowBase = blockIdx.x * 128;
    const int colBase = blockIdx.y * 256;

    float acc[2][8][4];
    #pragma unroll
    for (int i = 0; i < 2; i++)
        #pragma unroll
        for (int j = 0; j < 8; j++)
            #pragma unroll
            for (int u = 0; u < 4; u++) acc[i][j][u] = 0.f;

    const int nk = K >> 6;

    // ldmatrix lane addressing
    const int aRow = warp_m * 32 + (lane & 15);                      // + i*16
    const int aByte = (lane >> 4) << 4;                              // 0/16
    const int bRow = warp_n * 64 + ((lane >> 4) << 3) + (lane & 7);  // + jj*16
    const int bByte = ((lane >> 3) & 1) << 4;                        // 0/16

    auto fill = [&](int kt) {
        const uint32_t st = sbase + (kt % 3) * STAGE_BYTES;
        const int k0 = kt << 6;
        #pragma unroll
        for (int i = 0; i < 6; i++) {
            int o = tid + (i << 9);
            const __half* src;
            uint32_t dst;
            if (o < 1024) {
                int r = o >> 3, c = o & 7;
                src = aIn + (size_t)(rowBase + r) * K + k0 + c * 8;
                dst = st + swz(r * 128 + c * 16);
            } else {
                int q = o - 1024, r = q >> 3, c = q & 7;
                src = bW + (size_t)(colBase + r) * K + k0 + c * 8;
                dst = st + OFF_B + swz(r * 128 + c * 16);
            }
            cp_async16(dst, src);
        }
        cp_commit();
    };

    fill(0);
    fill(1);
    for (int kt = 0; kt < nk; kt++) {
        if (kt + 1 < nk) cp_wait<1>();
        else             cp_wait<0>();
        __syncthreads();
        if (kt + 2 < nk) fill(kt + 2);

        const uint32_t st = sbase + (kt % 3) * STAGE_BYTES;
        #pragma unroll
        for (int ks = 0; ks < 4; ks++) {
            uint32_t af[2][4], bf[8][2];
            #pragma unroll
            for (int i = 0; i < 2; i++)
                ldsm_x4(af[i][0], af[i][1], af[i][2], af[i][3],
                        st + swz((aRow + i * 16) * 128 + ks * 32 + aByte));
            #pragma unroll
            for (int jj = 0; jj < 4; jj++)
                ldsm_x4(bf[2*jj][0], bf[2*jj][1], bf[2*jj+1][0], bf[2*jj+1][1],
                        st + OFF_B + swz((bRow + jj * 16) * 128 + ks * 32 + bByte));
            #pragma unroll
            for (int i = 0; i < 2; i++)
                #pragma unroll
                for (int j = 0; j < 8; j++)
                    mma_f16(acc[i][j][0], acc[i][j][1], acc[i][j][2], acc[i][j][3],
                            af[i][0], af[i][1], af[i][2], af[i][3], bf[j][0], bf[j][1]);
        }
        __syncthreads();
    }

    // epilogue
    const int erow = rowBase + warp_m * 32 + (lane >> 2);
    const int ecol = colBase + warp_n * 64 + (lane & 3) * 2;
    #pragma unroll
    for (int i = 0; i < 2; i++) {
        #pragma unroll
        for (int j = 0; j < 8; j++) {
            int col = ecol + j * 8;
            float b0 = bias[col], b1 = bias[col + 1];
            #pragma unroll
            for (int h = 0; h < 2; h++) {
                int r = erow + i * 16 + h * 8;
                float x0 = epi_act<EPI>(acc[i][j][2 * h + 0] + b0);
                float x1 = epi_act<EPI>(acc[i][j][2 * h + 1] + b1);
                if (SPLIT == 0) {
                    *(float2*)(outF + (size_t)r * N + col) = make_float2(x0, x1);
                } else {
                    __half2 hv = __floats2half2_rn(x0, x1);
                    *(uint32_t*)(outH + (size_t)r * N + col) = *(uint32_t*)&hv;
                }
            }
        }
    }
}

// ---------------------------------------------------------------------------
// Launch
// ---------------------------------------------------------------------------
extern "C" void kernel_launch(void* const* d_in, const int* in_sizes, int n_in,
                              void* d_out, int out_size) {
    (void)in_sizes; (void)n_in; (void)out_size;

    const int*   ids  = (const int*)d_in[0];
    const float* tbl  = (const float*)d_in[1];
    const float* en_g = (const float*)d_in[2];
    const float* en_b = (const float*)d_in[3];
    const float* wA[2] = {(const float*)d_in[4],  (const float*)d_in[8]};
    const float* bA[2] = {(const float*)d_in[5],  (const float*)d_in[9]};
    const float* wB[2] = {(const float*)d_in[6],  (const float*)d_in[10]};
    const float* bB[2] = {(const float*)d_in[7],  (const float*)d_in[11]};
    const float* dw0 = (const float*)d_in[12];
    const float* db0 = (const float*)d_in[13];
    const float* fw0 = (const float*)d_in[14];
    const float* fb0 = (const float*)d_in[15];
    const float* iw0 = (const float*)d_in[16];
    const float* ib0 = (const float*)d_in[17];
    const float* cg0 = (const float*)d_in[18];
    const float* cb0 = (const float*)d_in[19];
    const float* ow = (const float*)d_in[28];
    const float* ob = (const float*)d_in[29];
    float* out = (float*)d_out;

    float *pdl, *pig;
    __half *act[2], *wt;
    cudaGetSymbolAddress((void**)&pdl,    g_dl);
    cudaGetSymbolAddress((void**)&pig,    g_ig);
    cudaGetSymbolAddress((void**)&act[0], g_act0);
    cudaGetSymbolAddress((void**)&act[1], g_act1);
    cudaGetSymbolAddress((void**)&wt,     g_wt);

    cudaFuncSetAttribute(gemm_f16<1, 1>, cudaFuncAttributeMaxDynamicSharedMemorySize, GEMM_SMEM);
    cudaFuncSetAttribute(gemm_f16<2, 0>, cudaFuncAttributeMaxDynamicSharedMemorySize, GEMM_SMEM);
    cudaFuncSetAttribute(gemm_f16<3, 0>, cudaFuncAttributeMaxDynamicSharedMemorySize, GEMM_SMEM);
    cudaFuncSetAttribute(gemm_f16<0, 0>, cudaFuncAttributeMaxDynamicSharedMemorySize, GEMM_SMEM);

    // weight arena offsets (elements): wA0 wB0 dw0 fw0 iw0 wA1 wB1 ow
    const long long EO_WA[2] = {0, 37748736};
    const long long EO_WB[2] = {8388608, 46137344};
    const long long EO_DW = 25165824, EO_FW = 29360128, EO_IW = 33554432;
    const long long EO_OW = 62914560;

    {
        WJobs jobs;
        const float* ws[NJOB] = {wA[0], wB[0], dw0, fw0, iw0, wA[1], wB[1], ow};
        const long long eo[NJOB] = {EO_WA[0], EO_WB[0], EO_DW, EO_FW, EO_IW,
                                    EO_WA[1], EO_WB[1], EO_OW};
        const int Ks[NJOB] = {2048, 4096, 4096, 4096, 4096, 2048, 4096, 4096};
        const int Ns[NJOB] = {4096, 4096, 1024, 1024, 1024, 4096, 4096, 32000};
        int cum = 0;
        for (int j = 0; j < NJOB; j++) {
            jobs.W[j] = ws[j]; jobs.off[j] = eo[j];
            jobs.K[j] = Ks[j]; jobs.N[j] = Ns[j];
            jobs.start[j] = cum;
            cum += (Ns[j] >> 5) * (Ks[j] >> 5);
        }
        jobs.start[NJOB] = cum;
        wsplit_all_kernel<<<cum, 256>>>(jobs, wt);
    }

    embed_ln_kernel<<<NTOK, 256>>>(ids, tbl, en_g, en_b);

    for (int blk = 0; blk < 2; blk++) {
        int p = blk & 1;
        int q = 1 - p;
        cat_half_kernel<<<NTOK * 2048 / 4 / 256, 256>>>(blk == 0 ? 1 : 0, act[p]);
        // h1 = relu(cat @ wA + bA) -> fp16
        gemm_f16<1, 1><<<dim3(NTOK / 128, HDIM / 256), 512, GEMM_SMEM>>>(
            act[p], wt + EO_WA[blk], bA[blk], nullptr, act[q], HDIM, EDIM + CDIM);
        // h2 = relu(h1 @ wB + bB) -> fp16
        gemm_f16<1, 1><<<dim3(NTOK / 128, HDIM / 256), 512, GEMM_SMEM>>>(
            act[q], wt + EO_WB[blk], bB[blk], nullptr, act[p], HDIM, HDIM);
        if (blk == 0) {
            // gates (f-gate dead: ctx starts at zero)
            gemm_f16<2, 0><<<dim3(NTOK / 128, CDIM / 256), 512, GEMM_SMEM>>>(
                act[p], wt + EO_DW, db0, pdl, nullptr, CDIM, HDIM);
            gemm_f16<3, 0><<<dim3(NTOK / 128, CDIM / 256), 512, GEMM_SMEM>>>(
                act[p], wt + EO_IW, ib0, pig, nullptr, CDIM, HDIM);
            (void)fw0; (void)fb0;
            ctx_update_kernel<<<NTOK, 256>>>(cg0, cb0);
        }
    }

    // logits = h2(block 1) @ ow + ob   (h2 of block 1 in parity-1 buffer)
    gemm_f16<0, 0><<<dim3(NTOK / 128, VDIM / 256), 512, GEMM_SMEM>>>(
        act[1], wt + EO_OW, ob, out, nullptr, VDIM, HDIM);
}

// round 12
// speedup vs baseline: 8.8751x; 1.0753x over previous
#include <cuda_runtime.h>
#include <cuda_fp16.h>
#include <cstdint>
#include <math.h>

#define NTOK 4096
#define EDIM 1024
#define CDIM 1024
#define HDIM 4096
#define VDIM 32000
#define EPS_LN 1e-5f

// ---------------------------------------------------------------------------
// Static scratch
// ---------------------------------------------------------------------------
__device__ float g_x[NTOK * EDIM];
__device__ float g_ctx[NTOK * CDIM];
__device__ float g_dl[NTOK * CDIM];
__device__ float g_ig[NTOK * CDIM];

// activation ping-pong buffers, fp16
__device__ __half g_act0[NTOK * HDIM];
__device__ __half g_act1[NTOK * HDIM];

// transposed weights [N,K], fp16 (7 live jobs; fw0 + block-1 gates dead)
#define WT_TOTAL 193986560ULL
__device__ __half g_wt[WT_TOTAL];

// ---------------------------------------------------------------------------
// helpers
// ---------------------------------------------------------------------------
__device__ __forceinline__ uint32_t smem_to_u32(const void* p) {
    uint32_t a;
    asm("{ .reg .u64 t; cvta.to.shared.u64 t, %1; cvt.u32.u64 %0, t; }"
        : "=r"(a) : "l"(p));
    return a;
}
__device__ __forceinline__ uint32_t swz(uint32_t o) { return o ^ ((o >> 3) & 0x70); }
__device__ __forceinline__ void cp_async16(uint32_t dst, const void* src) {
    asm volatile("cp.async.cg.shared.global [%0], [%1], 16;" :: "r"(dst), "l"(src));
}
template <int N>
__device__ __forceinline__ void cp_wait() {
    asm volatile("cp.async.wait_group %0;" :: "n"(N) : "memory");
}
__device__ __forceinline__ void cp_commit() {
    asm volatile("cp.async.commit_group;" ::: "memory");
}
__device__ __forceinline__ void ldsm_x4(uint32_t& a0, uint32_t& a1, uint32_t& a2,
                                        uint32_t& a3, uint32_t addr) {
    asm volatile("ldmatrix.sync.aligned.m8n8.x4.shared.b16 {%0,%1,%2,%3}, [%4];"
                 : "=r"(a0), "=r"(a1), "=r"(a2), "=r"(a3) : "r"(addr));
}
// fp16 MMA, fp32 accumulators
__device__ __forceinline__ void mma_f16(float& d0, float& d1, float& d2, float& d3,
                                        uint32_t a0, uint32_t a1, uint32_t a2, uint32_t a3,
                                        uint32_t b0, uint32_t b1) {
    asm volatile(
        "mma.sync.aligned.m16n8k16.row.col.f32.f16.f16.f32 "
        "{%0,%1,%2,%3}, {%4,%5,%6,%7}, {%8,%9}, {%0,%1,%2,%3};"
        : "+f"(d0), "+f"(d1), "+f"(d2), "+f"(d3)
        : "r"(a0), "r"(a1), "r"(a2), "r"(a3), "r"(b0), "r"(b1));
}

// ---------------------------------------------------------------------------
// block reductions (256 threads)
// ---------------------------------------------------------------------------
__device__ __forceinline__ float block_sum256(float val) {
    __shared__ float sh[8];
    int lane = threadIdx.x & 31;
    #pragma unroll
    for (int o = 16; o > 0; o >>= 1) val += __shfl_xor_sync(0xffffffffu, val, o);
    if (lane == 0) sh[threadIdx.x >> 5] = val;
    __syncthreads();
    float t = (lane < 8) ? sh[lane] : 0.f;
    #pragma unroll
    for (int o = 4; o > 0; o >>= 1) t += __shfl_xor_sync(0xffffffffu, t, o);
    t = __shfl_sync(0xffffffffu, t, 0);
    __syncthreads();
    return t;
}

// ---------------------------------------------------------------------------
// small kernels
// ---------------------------------------------------------------------------
__global__ void embed_ln_kernel(const int* __restrict__ ids,
                                const float* __restrict__ tbl,
                                const float* __restrict__ gw,
                                const float* __restrict__ gb) {
    int row = blockIdx.x;
    size_t base = (size_t)ids[row] * EDIM;
    float v[4];
    float s = 0.f;
    #pragma unroll
    for (int i = 0; i < 4; i++) { v[i] = tbl[base + threadIdx.x + i * 256]; s += v[i]; }
    float mean = block_sum256(s) * (1.f / (float)EDIM);
    float s2 = 0.f;
    #pragma unroll
    for (int i = 0; i < 4; i++) { float d = v[i] - mean; s2 += d * d; }
    float rstd = rsqrtf(block_sum256(s2) * (1.f / (float)EDIM) + EPS_LN);
    #pragma unroll
    for (int i = 0; i < 4; i++) {
        int c = threadIdx.x + i * 256;
        g_x[(size_t)row * EDIM + c] = (v[i] - mean) * rstd * gw[c] + gb[c];
    }
}

// ctx = LN(i*delta) for block 0 (ctx starts at zero -> f-gate term vanishes)
__global__ void ctx_update_kernel(const float* __restrict__ cg,
                                  const float* __restrict__ cb) {
    int row = blockIdx.x;
    size_t b = (size_t)row * CDIM;
    float v[4];
    float s = 0.f;
    #pragma unroll
    for (int i = 0; i < 4; i++) {
        int c = threadIdx.x + i * 256;
        v[i] = g_ig[b + c] * g_dl[b + c];
        s += v[i];
    }
    float mean = block_sum256(s) * (1.f / (float)CDIM);
    float s2 = 0.f;
    #pragma unroll
    for (int i = 0; i < 4; i++) { float d = v[i] - mean; s2 += d * d; }
    float rstd = rsqrtf(block_sum256(s2) * (1.f / (float)CDIM) + EPS_LN);
    #pragma unroll
    for (int i = 0; i < 4; i++) {
        int c = threadIdx.x + i * 256;
        g_ctx[b + c] = (v[i] - mean) * rstd * cg[c] + cb[c];
    }
}

// cat = [x | (first ? 0 : ctx)] -> fp16, row stride 2048
__global__ void cat_half_kernel(int first, __half* __restrict__ dst) {
    int idx = blockIdx.x * blockDim.x + threadIdx.x;
    int row = idx >> 9, c4 = idx & 511;
    float4 v;
    if (c4 < 256)      v = ((const float4*)g_x)[row * 256 + c4];
    else if (first)    v = make_float4(0.f, 0.f, 0.f, 0.f);
    else               v = ((const float4*)g_ctx)[row * 256 + (c4 - 256)];
    __half2 h0 = __floats2half2_rn(v.x, v.y);
    __half2 h1 = __floats2half2_rn(v.z, v.w);
    *(uint2*)(dst + (size_t)row * 2048 + c4 * 4) =
        make_uint2(*(uint32_t*)&h0, *(uint32_t*)&h1);
}

// ---------------------------------------------------------------------------
// Fused weight conversion: 7 live jobs, W[K,N] fp32 -> Wt[N,K] fp16
// (dw0 and iw0 placed contiguously so the gate GEMM sees one [2048,K] matrix)
// ---------------------------------------------------------------------------
#define NJOB 7
struct WJobs {
    const float* W[NJOB];
    long long off[NJOB];
    int K[NJOB];
    int N[NJOB];
    int start[NJOB + 1];
};

__global__ void wsplit_all_kernel(WJobs jobs, __half* __restrict__ T) {
    __shared__ float t[32][33];
    int b = blockIdx.x;
    int ji = 0;
    #pragma unroll
    for (int j = 0; j < NJOB; j++) if (b >= jobs.start[j + 1]) ji = j + 1;
    const float* W = jobs.W[ji];
    const int K = jobs.K[ji], N = jobs.N[ji];
    const long long off = jobs.off[ji];
    int tno = b - jobs.start[ji];
    int ntiles = N >> 5;
    int n0 = (tno % ntiles) << 5, k0 = (tno / ntiles) << 5;
    int tx = threadIdx.x & 31, ty = threadIdx.x >> 5;
    #pragma unroll
    for (int i = 0; i < 4; i++) {
        int kk = ty + i * 8;
        t[kk][tx] = W[(size_t)(k0 + kk) * N + n0 + tx];
    }
    __syncthreads();
    #pragma unroll
    for (int i = 0; i < 4; i++) {
        int nn = ty + i * 8;
        T[(size_t)off + (size_t)(n0 + nn) * K + k0 + tx] = __float2half(t[tx][nn]);
    }
}

// ---------------------------------------------------------------------------
// fp16 GEMM (single-pass): C[M,N] = act(A @ W^T + bias)
// Block tile 128x128, BK=64. 256 threads = 8 warps (2m x 4n), warp 64x32.
// Stage: A(16K)|B(16K) = 32KB; 3-stage pipeline = 96KB -> 2 CTAs/SM.
// ONE __syncthreads per k-tile (stage refilled at kt is last read at kt-1,
// ordered by this iteration's top barrier).
// EPI: 0 none->f32, 1 relu->f16, 4 gate-pair (cols<1024: tanh+bias -> outF,
//      cols>=1024: sigmoid+bias2 -> outF2; both row-stride 1024).
// ---------------------------------------------------------------------------
#define STAGE_BYTES 32768
#define OFF_B 16384
#define GEMM_SMEM (3 * STAGE_BYTES)

template <int EPI, int SPLIT>
__global__ void __launch_bounds__(256, 2)
gemm_f16(const __half* __restrict__ aIn, const __half* __restrict__ bW,
         const float* __restrict__ bias, const float* __restrict__ bias2,
         float* __restrict__ outF, float* __restrict__ outF2,
         __half* __restrict__ outH,
         int N, int K) {
    extern __shared__ char smem[];
    const uint32_t sbase = smem_to_u32(smem);
    const int tid = threadIdx.x, wid = tid >> 5, lane = tid & 31;
    const int warp_m = wid & 1, warp_n = wid >> 1;   // 2m x 4n
    const int rowBase = blockIdx.x * 128;
    const int colBase = blockIdx.y * 128;

    float acc[4][4][4];
    #pragma unroll
    for (int i = 0; i < 4; i++)
        #pragma unroll
        for (int j = 0; j < 4; j++)
            #pragma unroll
            for (int u = 0; u < 4; u++) acc[i][j][u] = 0.f;

    const int nk = K >> 6;

    // ldmatrix lane addressing
    const int aRow = warp_m * 64 + (lane & 15);                      // + i*16
    const int aByte = (lane >> 4) << 4;                              // 0/16
    const int bRow = warp_n * 32 + ((lane >> 4) << 3) + (lane & 7);  // + jj*16
    const int bByte = ((lane >> 3) & 1) << 4;                        // 0/16

    auto fill = [&](int kt) {
        const uint32_t st = sbase + (kt % 3) * STAGE_BYTES;
        const int k0 = kt << 6;
        #pragma unroll
        for (int i = 0; i < 8; i++) {
            int o = tid + (i << 8);
            int q = o & 1023, r = q >> 3, c = q & 7;
            const __half* src;
            uint32_t dst;
            if (o < 1024) {
                src = aIn + (size_t)(rowBase + r) * K + k0 + c * 8;
                dst = st + swz(r * 128 + c * 16);
            } else {
                src = bW + (size_t)(colBase + r) * K + k0 + c * 8;
                dst = st + OFF_B + swz(r * 128 + c * 16);
            }
            cp_async16(dst, src);
        }
        cp_commit();
    };

    fill(0);
    fill(1);
    for (int kt = 0; kt < nk; kt++) {
        if (kt + 1 < nk) cp_wait<1>();
        else             cp_wait<0>();
        __syncthreads();
        if (kt + 2 < nk) fill(kt + 2);

        const uint32_t st = sbase + (kt % 3) * STAGE_BYTES;
        #pragma unroll
        for (int ks = 0; ks < 4; ks++) {
            uint32_t af[4][4], bf[4][2];
            #pragma unroll
            for (int i = 0; i < 4; i++)
                ldsm_x4(af[i][0], af[i][1], af[i][2], af[i][3],
                        st + swz((aRow + i * 16) * 128 + ks * 32 + aByte));
            #pragma unroll
            for (int jj = 0; jj < 2; jj++)
                ldsm_x4(bf[2*jj][0], bf[2*jj][1], bf[2*jj+1][0], bf[2*jj+1][1],
                        st + OFF_B + swz((bRow + jj * 16) * 128 + ks * 32 + bByte));
            #pragma unroll
            for (int i = 0; i < 4; i++)
                #pragma unroll
                for (int j = 0; j < 4; j++)
                    mma_f16(acc[i][j][0], acc[i][j][1], acc[i][j][2], acc[i][j][3],
                            af[i][0], af[i][1], af[i][2], af[i][3], bf[j][0], bf[j][1]);
        }
        // single barrier per k-tile: protects stage (kt+1)%3 reads next iter;
        // the refill target (kt+2)%3 was last read at kt-1, already ordered.
        __syncthreads();
    }

    // epilogue
    const int erow = rowBase + warp_m * 64 + (lane >> 2);
    const int ecol = colBase + warp_n * 32 + (lane & 3) * 2;
    #pragma unroll
    for (int i = 0; i < 4; i++) {
        #pragma unroll
        for (int j = 0; j < 4; j++) {
            int col = ecol + j * 8;
            #pragma unroll
            for (int h = 0; h < 2; h++) {
                int r = erow + i * 16 + h * 8;
                float a0 = acc[i][j][2 * h + 0];
                float a1 = acc[i][j][2 * h + 1];
                if (EPI == 4) {
                    bool lo = col < 1024;
                    const float* bs = lo ? bias : bias2;
                    float* op = lo ? outF : outF2;
                    int cc = lo ? col : col - 1024;
                    float x0 = a0 + bs[cc], x1 = a1 + bs[cc + 1];
                    if (lo) { x0 = tanhf(x0); x1 = tanhf(x1); }
                    else    { x0 = 1.f / (1.f + expf(-x0)); x1 = 1.f / (1.f + expf(-x1)); }
                    *(float2*)(op + (size_t)r * 1024 + cc) = make_float2(x0, x1);
                } else {
                    float x0 = a0 + bias[col], x1 = a1 + bias[col + 1];
                    if (EPI == 1) { x0 = fmaxf(x0, 0.f); x1 = fmaxf(x1, 0.f); }
                    if (SPLIT == 0) {
                        *(float2*)(outF + (size_t)r * N + col) = make_float2(x0, x1);
                    } else {
                        __half2 hv = __floats2half2_rn(x0, x1);
                        *(uint32_t*)(outH + (size_t)r * N + col) = *(uint32_t*)&hv;
                    }
                }
            }
        }
    }
}

// ---------------------------------------------------------------------------
// Launch
// ---------------------------------------------------------------------------
extern "C" void kernel_launch(void* const* d_in, const int* in_sizes, int n_in,
                              void* d_out, int out_size) {
    (void)in_sizes; (void)n_in; (void)out_size;

    const int*   ids  = (const int*)d_in[0];
    const float* tbl  = (const float*)d_in[1];
    const float* en_g = (const float*)d_in[2];
    const float* en_b = (const float*)d_in[3];
    const float* wA[2] = {(const float*)d_in[4],  (const float*)d_in[8]};
    const float* bA[2] = {(const float*)d_in[5],  (const float*)d_in[9]};
    const float* wB[2] = {(const float*)d_in[6],  (const float*)d_in[10]};
    const float* bB[2] = {(const float*)d_in[7],  (const float*)d_in[11]};
    const float* dw0 = (const float*)d_in[12];
    const float* db0 = (const float*)d_in[13];
    const float* iw0 = (const float*)d_in[16];
    const float* ib0 = (const float*)d_in[17];
    const float* cg0 = (const float*)d_in[18];
    const float* cb0 = (const float*)d_in[19];
    const float* ow = (const float*)d_in[28];
    const float* ob = (const float*)d_in[29];
    float* out = (float*)d_out;

    float *pdl, *pig;
    __half *act[2], *wt;
    cudaGetSymbolAddress((void**)&pdl,    g_dl);
    cudaGetSymbolAddress((void**)&pig,    g_ig);
    cudaGetSymbolAddress((void**)&act[0], g_act0);
    cudaGetSymbolAddress((void**)&act[1], g_act1);
    cudaGetSymbolAddress((void**)&wt,     g_wt);

    cudaFuncSetAttribute(gemm_f16<1, 1>, cudaFuncAttributeMaxDynamicSharedMemorySize, GEMM_SMEM);
    cudaFuncSetAttribute(gemm_f16<4, 0>, cudaFuncAttributeMaxDynamicSharedMemorySize, GEMM_SMEM);
    cudaFuncSetAttribute(gemm_f16<0, 0>, cudaFuncAttributeMaxDynamicSharedMemorySize, GEMM_SMEM);

    // weight arena offsets (elements): wA0 wB0 dw0 iw0 wA1 wB1 ow
    const long long EO_WA[2] = {0, 33554432};
    const long long EO_WB[2] = {8388608, 41943040};
    const long long EO_GATE = 25165824;            // dw0 | iw0 contiguous
    const long long EO_OW = 58720256;

    {
        WJobs jobs;
        const float* ws[NJOB] = {wA[0], wB[0], dw0, iw0, wA[1], wB[1], ow};
        const long long eo[NJOB] = {EO_WA[0], EO_WB[0], EO_GATE, EO_GATE + 4194304,
                                    EO_WA[1], EO_WB[1], EO_OW};
        const int Ks[NJOB] = {2048, 4096, 4096, 4096, 2048, 4096, 4096};
        const int Ns[NJOB] = {4096, 4096, 1024, 1024, 4096, 4096, 32000};
        int cum = 0;
        for (int j = 0; j < NJOB; j++) {
            jobs.W[j] = ws[j]; jobs.off[j] = eo[j];
            jobs.K[j] = Ks[j]; jobs.N[j] = Ns[j];
            jobs.start[j] = cum;
            cum += (Ns[j] >> 5) * (Ks[j] >> 5);
        }
        jobs.start[NJOB] = cum;
        wsplit_all_kernel<<<cum, 256>>>(jobs, wt);
    }

    embed_ln_kernel<<<NTOK, 256>>>(ids, tbl, en_g, en_b);

    for (int blk = 0; blk < 2; blk++) {
        int p = blk & 1;
        int q = 1 - p;
        cat_half_kernel<<<NTOK * 2048 / 4 / 256, 256>>>(blk == 0 ? 1 : 0, act[p]);
        // h1 = relu(cat @ wA + bA) -> fp16
        gemm_f16<1, 1><<<dim3(NTOK / 128, HDIM / 128), 256, GEMM_SMEM>>>(
            act[p], wt + EO_WA[blk], bA[blk], nullptr,
            nullptr, nullptr, act[q], HDIM, EDIM + CDIM);
        // h2 = relu(h1 @ wB + bB) -> fp16
        gemm_f16<1, 1><<<dim3(NTOK / 128, HDIM / 128), 256, GEMM_SMEM>>>(
            act[q], wt + EO_WB[blk], bB[blk], nullptr,
            nullptr, nullptr, act[p], HDIM, HDIM);
        if (blk == 0) {
            // merged gates: N=2048 (delta|i), epilogue splits tanh/sigmoid
            gemm_f16<4, 0><<<dim3(NTOK / 128, 2048 / 128), 256, GEMM_SMEM>>>(
                act[p], wt + EO_GATE, db0, ib0,
                pdl, pig, nullptr, 2048, HDIM);
            ctx_update_kernel<<<NTOK, 256>>>(cg0, cb0);
        }
    }

    // logits = h2(block 1) @ ow + ob
    gemm_f16<0, 0><<<dim3(NTOK / 128, VDIM / 128), 256, GEMM_SMEM>>>(
        act[1], wt + EO_OW, ob, nullptr,
        out, nullptr, nullptr, VDIM, HDIM);
}